// round 3
// baseline (speedup 1.0000x reference)
#include <cuda_runtime.h>
#include <math.h>
#include <stdint.h>

#define BSZ 64
#define TT  512
#define DD  768
#define WW  255
#define HH  8
#define DHD 96
#define BW  (BSZ*WW)      // 16320
#define DFF 3072
#define MPAD 16384

// ---------------- scratch (device globals; no allocation allowed) ----------
static __device__ float g_feat[BW*DD];
static __device__ float g_q[BW*DD];
static __device__ float g_k[BW*DD];
static __device__ float g_v[BW*DD];
static __device__ float g_ctx[BW*DD];
static __device__ float g_tmp[BW*DD];
static __device__ float g_x[BW*DD];
static __device__ float g_x2[BW*DD];
static __device__ float g_ff1[(long)BW*DFF];
static __device__ int   g_first[BW];
static __device__ float g_aexp[(long)MPAD*3*DFF];   // 16384 x 9216 max
static __device__ float g_wq[DD*3*DD];
static __device__ float g_wk[DD*3*DD];
static __device__ float g_wv[DD*3*DD];
static __device__ float g_wo[DD*3*DD];
static __device__ float g_w1[DFF*3*DD];             // [3072][2304]
static __device__ float g_w2[DD*3*DFF];             // [768][9216]

// ---------------- helpers ----------------------------------------------------
__device__ __forceinline__ float tf32r(float x){
    float r; asm("cvt.rna.tf32.f32 %0, %1;" : "=f"(r) : "f"(x)); return r;
}
#define CP16(d,s)  asm volatile("cp.async.cg.shared.global [%0], [%1], 16;" :: "r"(d), "l"(s))
#define CPCOMMIT() asm volatile("cp.async.commit_group;" ::: "memory")
#define CPWAIT2()  asm volatile("cp.async.wait_group 2;" ::: "memory")

__device__ __forceinline__ uint32_t smem_u32(const void* p){
    uint32_t a;
    asm("{ .reg .u64 t; cvta.to.shared.u64 t, %1; cvt.u32.u64 %0, t; }" : "=r"(a) : "l"(p));
    return a;
}

__device__ __forceinline__ void mma_tf32(float* c, const uint32_t* a, const uint32_t* b){
    asm volatile(
        "mma.sync.aligned.m16n8k8.row.col.f32.tf32.tf32.f32 "
        "{%0,%1,%2,%3}, {%4,%5,%6,%7}, {%8,%9}, {%0,%1,%2,%3};"
        : "+f"(c[0]), "+f"(c[1]), "+f"(c[2]), "+f"(c[3])
        : "r"(a[0]), "r"(a[1]), "r"(a[2]), "r"(a[3]), "r"(b[0]), "r"(b[1]));
}

// ---------------- first-subtoken gather ------------------------------------
__global__ void init_first_k(int* first) {
    int i = blockIdx.x * blockDim.x + threadIdx.x;
    if (i < BW) first[i] = 0x7FFFFFFF;
}
__global__ void scan_first_k(const int* __restrict__ wi, int* __restrict__ first) {
    int i = blockIdx.x * blockDim.x + threadIdx.x;
    if (i < BSZ * TT) {
        int w = wi[i];
        if (w >= 0 && w < WW) atomicMin(&first[(i / TT) * WW + w], i % TT);
    }
}
__global__ void gather_k(const float* __restrict__ ob, const int* __restrict__ first,
                         float* __restrict__ feat) {
    int bw = blockIdx.x;
    int t = first[bw];
    if (t >= TT) t = 0;
    int b = bw / WW;
    const float4* src = (const float4*)(ob + ((long)(b * TT + t)) * DD);
    float4* dst = (float4*)(feat + (long)bw * DD);
    dst[threadIdx.x] = src[threadIdx.x];
}

// ---------------- split A into [Ah | Ah | Al] -------------------------------
__global__ void split_a_k(const float* __restrict__ src, float* __restrict__ dst, int K) {
    int row = blockIdx.y;
    int k = blockIdx.x * 256 + threadIdx.x;
    float v = src[(long)row * K + k];
    float h = tf32r(v);
    float l = tf32r(v - h);
    long b = (long)row * (3 * K);
    dst[b + k] = h;
    dst[b + K + k] = h;
    dst[b + 2 * K + k] = l;
}

// ---------------- transpose + split W[K,N] -> B' [N, 3K] = [Bh|Bl|Bh] -------
__global__ void trans_split_b_k(const float* __restrict__ W, float* __restrict__ Bx,
                                int K, int N) {
    __shared__ float t[32][33];
    int n0 = blockIdx.x * 32, k0 = blockIdx.y * 32;
    int tx = threadIdx.x & 31, ty = threadIdx.x >> 5;
    #pragma unroll
    for (int r = ty; r < 32; r += 8)
        t[r][tx] = W[(long)(k0 + r) * N + n0 + tx];
    __syncthreads();
    #pragma unroll
    for (int r = ty; r < 32; r += 8) {
        float v = t[tx][r];      // = W[k0+tx][n0+r]
        float h = tf32r(v);
        float l = tf32r(v - h);
        long b = (long)(n0 + r) * (3 * K) + k0 + tx;
        Bx[b] = h;
        Bx[b + K] = l;
        Bx[b + 2 * K] = h;
    }
}

// ---------------- mma.sync tf32 GEMM: C[M,N] = A'[M,Kp] @ B'[N,Kp]^T + bias -
// CTA tile 128x128xBK32, 4-stage cp.async, 8 warps (2M x 4N), warp 64x32.
#define GSTG 4
#define ASTRIDE 36
#define STG_FLOATS (2 * 128 * ASTRIDE)          // A + B per stage = 9216 floats
#define STG_BYTES  (STG_FLOATS * 4)             // 36864
#define GEMM_SMEM  (GSTG * STG_BYTES)           // 147456

__global__ __launch_bounds__(256)
void gemm_mma_k(const float* __restrict__ A, const float* __restrict__ Bm,
                const float* __restrict__ bias, float* __restrict__ C,
                int M, int N, int Kp, int relu)
{
    extern __shared__ float smf[];
    uint32_t sb = smem_u32(smf);
    int tid = threadIdx.x, wid = tid >> 5, lane = tid & 31;
    int g = lane >> 2, tg = lane & 3;
    int wm = wid & 1, wn = wid >> 1;

    const int S = Kp >> 5;
    const long mrow0 = (long)blockIdx.y * 128;
    const long nrow0 = (long)blockIdx.x * 128;
    const float* A0 = A + mrow0 * Kp;
    const float* B0 = Bm + nrow0 * Kp;

    float acc[4][4][4];
    #pragma unroll
    for (int i = 0; i < 4; i++)
        #pragma unroll
        for (int j = 0; j < 4; j++)
            #pragma unroll
            for (int r = 0; r < 4; r++) acc[i][j][r] = 0.f;

    // row/col this thread copies (4 chunks for A, 4 for B per stage)
    #define LOAD_STAGE(ks, slot) do { \
        uint32_t stA_ = sb + (slot) * STG_BYTES; \
        uint32_t stB_ = stA_ + 128 * ASTRIDE * 4; \
        const float* ab_ = A0 + (long)(ks) * 32; \
        const float* bb_ = B0 + (long)(ks) * 32; \
        _Pragma("unroll") \
        for (int i_ = 0; i_ < 4; i_++) { \
            int c_ = i_ * 256 + tid; \
            int r_ = c_ >> 3, q_ = c_ & 7; \
            uint32_t off_ = (uint32_t)(r_ * (ASTRIDE * 4) + q_ * 16); \
            CP16(stA_ + off_, ab_ + (long)r_ * Kp + q_ * 4); \
            CP16(stB_ + off_, bb_ + (long)r_ * Kp + q_ * 4); \
        } \
    } while (0)

    for (int s = 0; s < GSTG - 1; s++) { LOAD_STAGE(s, s); CPCOMMIT(); }

    for (int it = 0; it < S; it++) {
        int slot = it & (GSTG - 1);
        CPWAIT2();
        __syncthreads();
        int lt = it + GSTG - 1;
        if (lt < S) { LOAD_STAGE(lt, lt & (GSTG - 1)); }
        CPCOMMIT();

        const float* As = smf + slot * STG_FLOATS;
        const float* Bs = As + 128 * ASTRIDE;

        #pragma unroll
        for (int ks = 0; ks < 4; ks++) {
            int k0 = ks * 8;
            uint32_t a[4][4], b[4][2];
            #pragma unroll
            for (int mf = 0; mf < 4; mf++) {
                int r = wm * 64 + mf * 16 + g;
                const uint32_t* ap = (const uint32_t*)&As[r * ASTRIDE + k0 + tg];
                a[mf][0] = ap[0];
                a[mf][1] = ap[8 * ASTRIDE];
                a[mf][2] = ap[4];
                a[mf][3] = ap[8 * ASTRIDE + 4];
            }
            #pragma unroll
            for (int nf = 0; nf < 4; nf++) {
                int n = wn * 32 + nf * 8 + g;
                const uint32_t* bp = (const uint32_t*)&Bs[n * ASTRIDE + k0 + tg];
                b[nf][0] = bp[0];
                b[nf][1] = bp[4];
            }
            #pragma unroll
            for (int mf = 0; mf < 4; mf++)
                #pragma unroll
                for (int nf = 0; nf < 4; nf++)
                    mma_tf32(acc[mf][nf], a[mf], b[nf]);
        }
        __syncthreads();
    }

    // epilogue: direct stores, c0/c1 -> (row, col..col+1), c2/c3 -> row+8
    #pragma unroll
    for (int mf = 0; mf < 4; mf++) {
        long r0 = mrow0 + wm * 64 + mf * 16 + g;
        long r1 = r0 + 8;
        #pragma unroll
        for (int nf = 0; nf < 4; nf++) {
            long col = nrow0 + wn * 32 + nf * 8 + 2 * tg;
            float b0 = bias[col], b1 = bias[col + 1];
            float v0 = acc[mf][nf][0] + b0, v1 = acc[mf][nf][1] + b1;
            float v2 = acc[mf][nf][2] + b0, v3 = acc[mf][nf][3] + b1;
            if (relu) {
                v0 = fmaxf(v0, 0.f); v1 = fmaxf(v1, 0.f);
                v2 = fmaxf(v2, 0.f); v3 = fmaxf(v3, 0.f);
            }
            if (r0 < M) *(float2*)&C[r0 * N + col] = make_float2(v0, v1);
            if (r1 < M) *(float2*)&C[r1 * N + col] = make_float2(v2, v3);
        }
    }
}

// ---------------- fused attention: one block per (b,h) ---------------------
#define KPAD 97
#define ATTN_SMEM ((2*WW*KPAD + 8*DHD + 8*256) * 4)

__global__ __launch_bounds__(256)
void attn_k(const float* __restrict__ q, const float* __restrict__ k,
            const float* __restrict__ v, float* __restrict__ ctx) {
    int b = blockIdx.x / HH, h = blockIdx.x % HH;
    extern __shared__ float smfa[];
    float* ks = smfa;
    float* vs = ks + WW * KPAD;
    float* qs = vs + WW * KPAD;
    float* ps = qs + 8 * DHD;
    int tid = threadIdx.x, warp = tid >> 5, lane = tid & 31;

    for (int idx = tid; idx < WW * DHD; idx += 256) {
        int key = idx / DHD, d = idx % DHD;
        long gg = ((long)(b * WW + key)) * DD + h * DHD + d;
        ks[key * KPAD + d] = k[gg];
        vs[key * KPAD + d] = v[gg];
    }
    __syncthreads();

    const float scale = 0.10206207261596575f;

    for (int row0 = 0; row0 < WW; row0 += 8) {
        int row = row0 + warp;
        if (row < WW) {
            for (int d = lane; d < DHD; d += 32)
                qs[warp * DHD + d] = q[((long)(b * WW + row)) * DD + h * DHD + d];
        }
        __syncwarp();
        if (row < WW) {
            float sc[8];
            float m = -1e30f;
            #pragma unroll
            for (int kk = 0; kk < 8; kk++) {
                int key = lane + kk * 32;
                float s = -1e30f;
                if (key < WW) {
                    s = 0.f;
                    #pragma unroll 8
                    for (int d = 0; d < DHD; d++)
                        s += qs[warp * DHD + d] * ks[key * KPAD + d];
                    s *= scale;
                }
                sc[kk] = s;
                m = fmaxf(m, s);
            }
            #pragma unroll
            for (int o = 16; o; o >>= 1) m = fmaxf(m, __shfl_xor_sync(0xffffffffu, m, o));
            float sum = 0.f;
            #pragma unroll
            for (int kk = 0; kk < 8; kk++) {
                float e = (sc[kk] > -1e29f) ? __expf(sc[kk] - m) : 0.f;
                sc[kk] = e; sum += e;
            }
            #pragma unroll
            for (int o = 16; o; o >>= 1) sum += __shfl_xor_sync(0xffffffffu, sum, o);
            float inv = 1.f / sum;
            #pragma unroll
            for (int kk = 0; kk < 8; kk++) {
                int key = lane + kk * 32;
                if (key < 256) ps[warp * 256 + key] = sc[kk] * inv;
            }
        }
        __syncwarp();
        if (row < WW) {
            int d0 = lane * 3;
            float a0 = 0.f, a1 = 0.f, a2 = 0.f;
            for (int key = 0; key < WW; key++) {
                float p = ps[warp * 256 + key];
                const float* vr = &vs[key * KPAD + d0];
                a0 += p * vr[0];
                a1 += p * vr[1];
                a2 += p * vr[2];
            }
            float* o = &ctx[((long)(b * WW + row)) * DD + h * DHD + d0];
            o[0] = a0; o[1] = a1; o[2] = a2;
        }
        __syncwarp();
    }
}

// ---------------- block reduce helper ---------------------------------------
__device__ __forceinline__ float block_reduce_sum(float val, float* red) {
    int lane = threadIdx.x & 31, warp = threadIdx.x >> 5;
    #pragma unroll
    for (int o = 16; o; o >>= 1) val += __shfl_xor_sync(0xffffffffu, val, o);
    if (lane == 0) red[warp] = val;
    __syncthreads();
    if (warp == 0) {
        float v = (lane < 8) ? red[lane] : 0.f;
        #pragma unroll
        for (int o = 4; o; o >>= 1) v += __shfl_xor_sync(0xffffffffu, v, o);
        if (lane == 0) red[0] = v;
    }
    __syncthreads();
    float r = red[0];
    __syncthreads();
    return r;
}

// ---------------- residual add + layernorm ----------------------------------
__global__ __launch_bounds__(256)
void add_ln_k(const float* __restrict__ X, const float* __restrict__ Y,
              const float* __restrict__ g, const float* __restrict__ bb,
              float* __restrict__ out) {
    __shared__ float red[32];
    int row = blockIdx.x, tid = threadIdx.x;
    const float* x = X + (long)row * DD;
    const float* y = Y + (long)row * DD;
    float v[3];
    float s = 0.f;
    #pragma unroll
    for (int i = 0; i < 3; i++) {
        int c = tid + 256 * i;
        v[i] = x[c] + y[c];
        s += v[i];
    }
    float mean = block_reduce_sum(s, red) * (1.f / DD);
    float vs = 0.f;
    #pragma unroll
    for (int i = 0; i < 3; i++) { float d = v[i] - mean; vs += d * d; }
    float var = block_reduce_sum(vs, red) * (1.f / DD);
    float rstd = rsqrtf(var + 1e-5f);
    float* o = out + (long)row * DD;
    #pragma unroll
    for (int i = 0; i < 3; i++) {
        int c = tid + 256 * i;
        o[c] = (v[i] - mean) * rstd * g[c] + bb[c];
    }
}

// ---------------- final: LN + linear(2) + softmax + argmax ------------------
__global__ __launch_bounds__(256)
void final_k(const float* __restrict__ X, const float* __restrict__ g,
             const float* __restrict__ bb, const float* __restrict__ lw,
             const float* __restrict__ lb, float* __restrict__ probs,
             float* __restrict__ path, int write_path) {
    __shared__ float red[32];
    int row = blockIdx.x, tid = threadIdx.x;
    const float* x = X + (long)row * DD;
    float v[3];
    float s = 0.f;
    #pragma unroll
    for (int i = 0; i < 3; i++) { v[i] = x[tid + 256 * i]; s += v[i]; }
    float mean = block_reduce_sum(s, red) * (1.f / DD);
    float vs = 0.f;
    #pragma unroll
    for (int i = 0; i < 3; i++) { float d = v[i] - mean; vs += d * d; }
    float var = block_reduce_sum(vs, red) * (1.f / DD);
    float rstd = rsqrtf(var + 1e-5f);
    float l0 = 0.f, l1 = 0.f;
    #pragma unroll
    for (int i = 0; i < 3; i++) {
        int c = tid + 256 * i;
        float yv = (v[i] - mean) * rstd * g[c] + bb[c];
        l0 += yv * lw[2 * c + 0];
        l1 += yv * lw[2 * c + 1];
    }
    l0 = block_reduce_sum(l0, red);
    l1 = block_reduce_sum(l1, red);
    if (tid == 0) {
        l0 += lb[0]; l1 += lb[1];
        float m = fmaxf(l0, l1);
        float e0 = expf(l0 - m), e1 = expf(l1 - m);
        float inv = 1.f / (e0 + e1);
        probs[2 * row + 0] = e0 * inv;
        probs[2 * row + 1] = e1 * inv;
        if (write_path) path[row] = (l1 > l0) ? 1.f : 0.f;
    }
}

// ---------------- launch -----------------------------------------------------
extern "C" void kernel_launch(void* const* d_in, const int* in_sizes, int n_in,
                              void* d_out, int out_size) {
    const float* ob  = (const float*)d_in[0];
    const int*   wi  = (const int*)d_in[1];
    const float* Wq  = (const float*)d_in[2];   const float* bq  = (const float*)d_in[3];
    const float* Wk  = (const float*)d_in[4];   const float* bk  = (const float*)d_in[5];
    const float* Wv  = (const float*)d_in[6];   const float* bv  = (const float*)d_in[7];
    const float* Wo  = (const float*)d_in[8];   const float* bo  = (const float*)d_in[9];
    const float* l1g = (const float*)d_in[10];  const float* l1b = (const float*)d_in[11];
    const float* W1f = (const float*)d_in[12];  const float* b1f = (const float*)d_in[13];
    const float* W2f = (const float*)d_in[14];  const float* b2f = (const float*)d_in[15];
    const float* l2g = (const float*)d_in[16];  const float* l2b = (const float*)d_in[17];
    const float* ng  = (const float*)d_in[18];  const float* nb  = (const float*)d_in[19];
    const float* lw  = (const float*)d_in[20];  const float* lb  = (const float*)d_in[21];

    float *feat, *q, *k, *v, *ctx, *tmp, *x, *x2, *ff1, *aexp;
    float *wqx, *wkx, *wvx, *wox, *w1x, *w2x;
    int* first;
    cudaGetSymbolAddress((void**)&feat, g_feat);
    cudaGetSymbolAddress((void**)&q,    g_q);
    cudaGetSymbolAddress((void**)&k,    g_k);
    cudaGetSymbolAddress((void**)&v,    g_v);
    cudaGetSymbolAddress((void**)&ctx,  g_ctx);
    cudaGetSymbolAddress((void**)&tmp,  g_tmp);
    cudaGetSymbolAddress((void**)&x,    g_x);
    cudaGetSymbolAddress((void**)&x2,   g_x2);
    cudaGetSymbolAddress((void**)&ff1,  g_ff1);
    cudaGetSymbolAddress((void**)&aexp, g_aexp);
    cudaGetSymbolAddress((void**)&wqx,  g_wq);
    cudaGetSymbolAddress((void**)&wkx,  g_wk);
    cudaGetSymbolAddress((void**)&wvx,  g_wv);
    cudaGetSymbolAddress((void**)&wox,  g_wo);
    cudaGetSymbolAddress((void**)&w1x,  g_w1);
    cudaGetSymbolAddress((void**)&w2x,  g_w2);
    cudaGetSymbolAddress((void**)&first, g_first);

    cudaFuncSetAttribute(attn_k, cudaFuncAttributeMaxDynamicSharedMemorySize, ATTN_SMEM);
    cudaFuncSetAttribute(gemm_mma_k, cudaFuncAttributeMaxDynamicSharedMemorySize, GEMM_SMEM);

    // weight prep: transpose + tf32 split
    trans_split_b_k<<<dim3(DD/32, DD/32), 256>>>(Wq,  wqx, DD, DD);
    trans_split_b_k<<<dim3(DD/32, DD/32), 256>>>(Wk,  wkx, DD, DD);
    trans_split_b_k<<<dim3(DD/32, DD/32), 256>>>(Wv,  wvx, DD, DD);
    trans_split_b_k<<<dim3(DD/32, DD/32), 256>>>(Wo,  wox, DD, DD);
    trans_split_b_k<<<dim3(DFF/32, DD/32), 256>>>(W1f, w1x, DD, DFF);
    trans_split_b_k<<<dim3(DD/32, DFF/32), 256>>>(W2f, w2x, DFF, DD);

    // gather
    init_first_k<<<(BW + 255) / 256, 256>>>(first);
    scan_first_k<<<(BSZ * TT + 255) / 256, 256>>>(wi, first);
    gather_k<<<BW, 192>>>(ob, first, feat);

    // QKV projections (mma.sync tf32 3x-split)
    dim3 gDD(6, 128), gFF(24, 128);
    split_a_k<<<dim3(DD/256, BW), 256>>>(feat, aexp, DD);
    gemm_mma_k<<<gDD, 256, GEMM_SMEM>>>(aexp, wqx, bq, q, BW, DD, 3*DD, 0);
    gemm_mma_k<<<gDD, 256, GEMM_SMEM>>>(aexp, wkx, bk, k, BW, DD, 3*DD, 0);
    gemm_mma_k<<<gDD, 256, GEMM_SMEM>>>(aexp, wvx, bv, v, BW, DD, 3*DD, 0);

    // attention
    attn_k<<<BSZ * HH, 256, ATTN_SMEM>>>(q, k, v, ctx);

    // output proj + LN1
    split_a_k<<<dim3(DD/256, BW), 256>>>(ctx, aexp, DD);
    gemm_mma_k<<<gDD, 256, GEMM_SMEM>>>(aexp, wox, bo, tmp, BW, DD, 3*DD, 0);
    add_ln_k<<<BW, 256>>>(feat, tmp, l1g, l1b, x);

    // FFN + LN2
    split_a_k<<<dim3(DD/256, BW), 256>>>(x, aexp, DD);
    gemm_mma_k<<<gFF, 256, GEMM_SMEM>>>(aexp, w1x, b1f, ff1, BW, DFF, 3*DD, 1);
    split_a_k<<<dim3(DFF/256, BW), 256>>>(ff1, aexp, DFF);
    gemm_mma_k<<<gDD, 256, GEMM_SMEM>>>(aexp, w2x, b2f, tmp, BW, DD, 3*DFF, 0);
    add_ln_k<<<BW, 256>>>(x, tmp, l2g, l2b, x2);

    // final LN + linear + softmax + argmax
    float* probs = (float*)d_out;
    float* path  = probs + (long)BW * 2;
    int wp = (out_size >= BW * 3) ? 1 : 0;
    final_k<<<BW, 256>>>(x2, ng, nb, lw, lb, probs, path, wp);
}

// round 4
// speedup vs baseline: 1.7444x; 1.7444x over previous
#include <cuda_runtime.h>
#include <cuda_fp16.h>
#include <math.h>
#include <stdint.h>

#define BSZ 64
#define TT  512
#define DD  768
#define WW  255
#define HH  8
#define DHD 96
#define BW  (BSZ*WW)      // 16320
#define DFF 3072
#define MPAD 16384

// ---------------- scratch (device globals; no allocation allowed) ----------
static __device__ float  g_feat[BW*DD];
static __device__ float  g_q[BW*DD];
static __device__ float  g_k[BW*DD];
static __device__ float  g_v[BW*DD];
static __device__ float  g_ctx[BW*DD];
static __device__ float  g_tmp[BW*DD];
static __device__ float  g_x[BW*DD];
static __device__ float  g_x2[BW*DD];
static __device__ float  g_ff1[(long)BW*DFF];
static __device__ int    g_first[BW];
static __device__ __half g_aexp[(long)MPAD*2*DFF];    // [M, 2K] halfs, K<=3072
static __device__ __half g_wq[DD*2*DD];
static __device__ __half g_wk[DD*2*DD];
static __device__ __half g_wv[DD*2*DD];
static __device__ __half g_wo[DD*2*DD];
static __device__ __half g_w1[DFF*2*DD];              // [3072][1536]
static __device__ __half g_w2[DD*2*DFF];              // [768][6144]

// ---------------- helpers ----------------------------------------------------
#define CP16(d,s)  asm volatile("cp.async.cg.shared.global [%0], [%1], 16;" :: "r"(d), "l"(s))
#define CPCOMMIT() asm volatile("cp.async.commit_group;" ::: "memory")
#define CPWAIT1()  asm volatile("cp.async.wait_group 1;" ::: "memory")

__device__ __forceinline__ uint32_t smem_u32(const void* p){
    uint32_t a;
    asm("{ .reg .u64 t; cvta.to.shared.u64 t, %1; cvt.u32.u64 %0, t; }" : "=r"(a) : "l"(p));
    return a;
}

__device__ __forceinline__ void mma_f16(float* c, const uint32_t* a, const uint32_t* b){
    asm volatile(
        "mma.sync.aligned.m16n8k16.row.col.f32.f16.f16.f32 "
        "{%0,%1,%2,%3}, {%4,%5,%6,%7}, {%8,%9}, {%0,%1,%2,%3};"
        : "+f"(c[0]), "+f"(c[1]), "+f"(c[2]), "+f"(c[3])
        : "r"(a[0]), "r"(a[1]), "r"(a[2]), "r"(a[3]), "r"(b[0]), "r"(b[1]));
}

// ---------------- fused weight prep: transpose + fp16 hi/lo split -----------
// For each W[K,N]: Bx[n][k] = hi, Bx[n][K+k] = lo  (row stride 2K halfs)
__global__ void prep_weights_k(
    const float* __restrict__ Wq, const float* __restrict__ Wk,
    const float* __restrict__ Wv, const float* __restrict__ Wo,
    const float* __restrict__ W1, const float* __restrict__ W2,
    __half* wq, __half* wk, __half* wv, __half* wo, __half* w1, __half* w2)
{
    __shared__ float t[32][33];
    int z = blockIdx.z;
    const float* W; __half* Bx; int K, N;
    switch (z) {
        case 0: W = Wq; Bx = wq; K = DD;  N = DD;  break;
        case 1: W = Wk; Bx = wk; K = DD;  N = DD;  break;
        case 2: W = Wv; Bx = wv; K = DD;  N = DD;  break;
        case 3: W = Wo; Bx = wo; K = DD;  N = DD;  break;
        case 4: W = W1; Bx = w1; K = DD;  N = DFF; break;
        default:W = W2; Bx = w2; K = DFF; N = DD;  break;
    }
    int n0 = blockIdx.x * 32, k0 = blockIdx.y * 32;
    if (n0 >= N || k0 >= K) return;
    int tx = threadIdx.x & 31, ty = threadIdx.x >> 5;
    #pragma unroll
    for (int r = ty; r < 32; r += 8)
        t[r][tx] = W[(long)(k0 + r) * N + n0 + tx];
    __syncthreads();
    #pragma unroll
    for (int r = ty; r < 32; r += 8) {
        float v = t[tx][r];               // = W[k0+tx][n0+r]
        __half h = __float2half_rn(v);
        __half l = __float2half_rn(v - __half2float(h));
        long b = (long)(n0 + r) * (2 * K) + k0 + tx;
        Bx[b] = h;
        Bx[b + K] = l;
    }
}

// ---------------- first-subtoken gather ------------------------------------
__global__ void init_first_k(int* first) {
    int i = blockIdx.x * blockDim.x + threadIdx.x;
    if (i < BW) first[i] = 0x7FFFFFFF;
}
__global__ void scan_first_k(const int* __restrict__ wi, int* __restrict__ first) {
    int i = blockIdx.x * blockDim.x + threadIdx.x;
    if (i < BSZ * TT) {
        int w = wi[i];
        if (w >= 0 && w < WW) atomicMin(&first[(i / TT) * WW + w], i % TT);
    }
}
__global__ void gather_k(const float* __restrict__ ob, const int* __restrict__ first,
                         float* __restrict__ feat) {
    int bw = blockIdx.x;
    int t = first[bw];
    if (t >= TT) t = 0;
    int b = bw / WW;
    const float4* src = (const float4*)(ob + ((long)(b * TT + t)) * DD);
    float4* dst = (float4*)(feat + (long)bw * DD);
    dst[threadIdx.x] = src[threadIdx.x];
}

// ---------------- split A into [Ah | Al] halfs ------------------------------
__global__ void split_a_k(const float* __restrict__ src, __half* __restrict__ dst, int K) {
    int row = blockIdx.y;
    int k = blockIdx.x * 256 + threadIdx.x;
    float v = src[(long)row * K + k];
    __half h = __float2half_rn(v);
    __half l = __float2half_rn(v - __half2float(h));
    long b = (long)row * (2 * K);
    dst[b + k] = h;
    dst[b + K + k] = l;
}

// ---------------- fp16x3 GEMM: C[M,N] = A[M,K] @ W[K,N] + bias --------------
// A2 = [Ah|Al] halfs [M, 2K]; B2 = [Bh|Bl] halfs [N, 2K].
// C = Ah*Bh + Ah*Bl + Al*Bh (fp32 accum). CTA tile 128x256, warp 64x64.
#define KT 64                          // k-tile (halfs of original K)
#define SH 72                          // smem row stride in halfs (144B = 9*16)
#define A_HALFS (128*SH)               // 9216
#define B_HALFS (256*SH)               // 18432
#define STG_HALFS (2*A_HALFS + 2*B_HALFS)  // 55296
#define STG_BYTES (STG_HALFS*2)        // 110592
#define GEMM_SMEM (2*STG_BYTES)        // 221184

__global__ __launch_bounds__(256)
void gemm_f16_k(const __half* __restrict__ A2, const __half* __restrict__ B2,
                const float* __restrict__ bias, float* __restrict__ C,
                int M, int N, int K, int relu)
{
    extern __shared__ __half smh[];
    uint32_t sb = smem_u32(smh);
    int tid = threadIdx.x, wid = tid >> 5, lane = tid & 31;
    int g = lane >> 2, tg = lane & 3;
    int wm = wid & 1, wn = wid >> 1;           // 2 x 4 warps, warp tile 64x64
    const int K2 = 2 * K;
    const int S = K / KT;
    const long mrow0 = (long)blockIdx.y * 128;
    const long nrow0 = (long)blockIdx.x * 256;

    float acc[4][8][4];
    #pragma unroll
    for (int i = 0; i < 4; i++)
        #pragma unroll
        for (int j = 0; j < 8; j++)
            #pragma unroll
            for (int r = 0; r < 4; r++) acc[i][j][r] = 0.f;

    #define LOAD_STAGE(ks, slot) do { \
        uint32_t base_ = sb + (slot) * STG_BYTES; \
        _Pragma("unroll") \
        for (int i_ = 0; i_ < 4; i_++) { \
            int c_ = i_ * 256 + tid; int r_ = c_ >> 3, q_ = c_ & 7; \
            long grow_ = mrow0 + r_; if (grow_ >= M) grow_ = M - 1; \
            const __half* s_ = A2 + grow_ * K2 + (ks) * KT + q_ * 8; \
            uint32_t d_ = base_ + (uint32_t)(r_ * (SH*2) + q_ * 16); \
            CP16(d_, s_); \
            CP16(d_ + A_HALFS*2, s_ + K); \
        } \
        _Pragma("unroll") \
        for (int i_ = 0; i_ < 8; i_++) { \
            int c_ = i_ * 256 + tid; int r_ = c_ >> 3, q_ = c_ & 7; \
            const __half* s_ = B2 + (long)(nrow0 + r_) * K2 + (ks) * KT + q_ * 8; \
            uint32_t d_ = base_ + (uint32_t)(2*A_HALFS*2 + r_ * (SH*2) + q_ * 16); \
            CP16(d_, s_); \
            CP16(d_ + B_HALFS*2, s_ + K); \
        } \
    } while (0)

    LOAD_STAGE(0, 0); CPCOMMIT();

    for (int it = 0; it < S; it++) {
        int slot = it & 1;
        if (it + 1 < S) { LOAD_STAGE(it + 1, (it + 1) & 1); }
        CPCOMMIT();
        CPWAIT1();
        __syncthreads();

        const __half* sAh = smh + slot * STG_HALFS;
        const __half* sAl = sAh + A_HALFS;
        const __half* sBh = sAl + A_HALFS;
        const __half* sBl = sBh + B_HALFS;

        #pragma unroll
        for (int ks = 0; ks < 4; ks++) {
            int k0 = ks * 16;
            uint32_t a[4][4], bh[8][2], bl[8][2];
            #pragma unroll
            for (int mf = 0; mf < 4; mf++) {
                int r = wm * 64 + mf * 16 + g;
                const __half* ap = &sAh[r * SH + k0 + 2 * tg];
                a[mf][0] = *(const uint32_t*)(ap);
                a[mf][1] = *(const uint32_t*)(ap + 8 * SH);
                a[mf][2] = *(const uint32_t*)(ap + 8);
                a[mf][3] = *(const uint32_t*)(ap + 8 * SH + 8);
            }
            #pragma unroll
            for (int nf = 0; nf < 8; nf++) {
                int n = wn * 64 + nf * 8 + g;
                const __half* bp = &sBh[n * SH + k0 + 2 * tg];
                bh[nf][0] = *(const uint32_t*)(bp);
                bh[nf][1] = *(const uint32_t*)(bp + 8);
                const __half* bq = &sBl[n * SH + k0 + 2 * tg];
                bl[nf][0] = *(const uint32_t*)(bq);
                bl[nf][1] = *(const uint32_t*)(bq + 8);
            }
            #pragma unroll
            for (int mf = 0; mf < 4; mf++)
                #pragma unroll
                for (int nf = 0; nf < 8; nf++) {
                    mma_f16(acc[mf][nf], a[mf], bh[nf]);
                    mma_f16(acc[mf][nf], a[mf], bl[nf]);
                }
            // reload a-frags from Al, third product
            #pragma unroll
            for (int mf = 0; mf < 4; mf++) {
                int r = wm * 64 + mf * 16 + g;
                const __half* ap = &sAl[r * SH + k0 + 2 * tg];
                a[mf][0] = *(const uint32_t*)(ap);
                a[mf][1] = *(const uint32_t*)(ap + 8 * SH);
                a[mf][2] = *(const uint32_t*)(ap + 8);
                a[mf][3] = *(const uint32_t*)(ap + 8 * SH + 8);
            }
            #pragma unroll
            for (int mf = 0; mf < 4; mf++)
                #pragma unroll
                for (int nf = 0; nf < 8; nf++)
                    mma_f16(acc[mf][nf], a[mf], bh[nf]);
        }
        __syncthreads();
    }

    // epilogue
    #pragma unroll
    for (int mf = 0; mf < 4; mf++) {
        long r0 = mrow0 + wm * 64 + mf * 16 + g;
        long r1 = r0 + 8;
        #pragma unroll
        for (int nf = 0; nf < 8; nf++) {
            long col = nrow0 + wn * 64 + nf * 8 + 2 * tg;
            float b0 = bias[col], b1 = bias[col + 1];
            float v0 = acc[mf][nf][0] + b0, v1 = acc[mf][nf][1] + b1;
            float v2 = acc[mf][nf][2] + b0, v3 = acc[mf][nf][3] + b1;
            if (relu) {
                v0 = fmaxf(v0, 0.f); v1 = fmaxf(v1, 0.f);
                v2 = fmaxf(v2, 0.f); v3 = fmaxf(v3, 0.f);
            }
            if (r0 < M) *(float2*)&C[r0 * N + col] = make_float2(v0, v1);
            if (r1 < M) *(float2*)&C[r1 * N + col] = make_float2(v2, v3);
        }
    }
}

// ---------------- fused attention: one block per (b,h) ---------------------
#define KPAD 97
#define ATTN_SMEM ((2*WW*KPAD + 8*DHD + 8*256) * 4)

__global__ __launch_bounds__(256)
void attn_k(const float* __restrict__ q, const float* __restrict__ k,
            const float* __restrict__ v, float* __restrict__ ctx) {
    int b = blockIdx.x / HH, h = blockIdx.x % HH;
    extern __shared__ float smfa[];
    float* ks = smfa;
    float* vs = ks + WW * KPAD;
    float* qs = vs + WW * KPAD;
    float* ps = qs + 8 * DHD;
    int tid = threadIdx.x, warp = tid >> 5, lane = tid & 31;

    for (int idx = tid; idx < WW * DHD; idx += 256) {
        int key = idx / DHD, d = idx % DHD;
        long gg = ((long)(b * WW + key)) * DD + h * DHD + d;
        ks[key * KPAD + d] = k[gg];
        vs[key * KPAD + d] = v[gg];
    }
    __syncthreads();

    const float scale = 0.10206207261596575f;

    for (int row0 = 0; row0 < WW; row0 += 8) {
        int row = row0 + warp;
        if (row < WW) {
            for (int d = lane; d < DHD; d += 32)
                qs[warp * DHD + d] = q[((long)(b * WW + row)) * DD + h * DHD + d];
        }
        __syncwarp();
        if (row < WW) {
            float sc[8];
            float m = -1e30f;
            #pragma unroll
            for (int kk = 0; kk < 8; kk++) {
                int key = lane + kk * 32;
                float s = -1e30f;
                if (key < WW) {
                    s = 0.f;
                    #pragma unroll 8
                    for (int d = 0; d < DHD; d++)
                        s += qs[warp * DHD + d] * ks[key * KPAD + d];
                    s *= scale;
                }
                sc[kk] = s;
                m = fmaxf(m, s);
            }
            #pragma unroll
            for (int o = 16; o; o >>= 1) m = fmaxf(m, __shfl_xor_sync(0xffffffffu, m, o));
            float sum = 0.f;
            #pragma unroll
            for (int kk = 0; kk < 8; kk++) {
                float e = (sc[kk] > -1e29f) ? __expf(sc[kk] - m) : 0.f;
                sc[kk] = e; sum += e;
            }
            #pragma unroll
            for (int o = 16; o; o >>= 1) sum += __shfl_xor_sync(0xffffffffu, sum, o);
            float inv = 1.f / sum;
            #pragma unroll
            for (int kk = 0; kk < 8; kk++) {
                int key = lane + kk * 32;
                if (key < 256) ps[warp * 256 + key] = sc[kk] * inv;
            }
        }
        __syncwarp();
        if (row < WW) {
            int d0 = lane * 3;
            float a0 = 0.f, a1 = 0.f, a2 = 0.f;
            for (int key = 0; key < WW; key++) {
                float p = ps[warp * 256 + key];
                const float* vr = &vs[key * KPAD + d0];
                a0 += p * vr[0];
                a1 += p * vr[1];
                a2 += p * vr[2];
            }
            float* o = &ctx[((long)(b * WW + row)) * DD + h * DHD + d0];
            o[0] = a0; o[1] = a1; o[2] = a2;
        }
        __syncwarp();
    }
}

// ---------------- block reduce helper ---------------------------------------
__device__ __forceinline__ float block_reduce_sum(float val, float* red) {
    int lane = threadIdx.x & 31, warp = threadIdx.x >> 5;
    #pragma unroll
    for (int o = 16; o; o >>= 1) val += __shfl_xor_sync(0xffffffffu, val, o);
    if (lane == 0) red[warp] = val;
    __syncthreads();
    if (warp == 0) {
        float v = (lane < 8) ? red[lane] : 0.f;
        #pragma unroll
        for (int o = 4; o; o >>= 1) v += __shfl_xor_sync(0xffffffffu, v, o);
        if (lane == 0) red[0] = v;
    }
    __syncthreads();
    float r = red[0];
    __syncthreads();
    return r;
}

// ---------------- residual add + layernorm ----------------------------------
__global__ __launch_bounds__(256)
void add_ln_k(const float* __restrict__ X, const float* __restrict__ Y,
              const float* __restrict__ g, const float* __restrict__ bb,
              float* __restrict__ out) {
    __shared__ float red[32];
    int row = blockIdx.x, tid = threadIdx.x;
    const float* x = X + (long)row * DD;
    const float* y = Y + (long)row * DD;
    float v[3];
    float s = 0.f;
    #pragma unroll
    for (int i = 0; i < 3; i++) {
        int c = tid + 256 * i;
        v[i] = x[c] + y[c];
        s += v[i];
    }
    float mean = block_reduce_sum(s, red) * (1.f / DD);
    float vs = 0.f;
    #pragma unroll
    for (int i = 0; i < 3; i++) { float d = v[i] - mean; vs += d * d; }
    float var = block_reduce_sum(vs, red) * (1.f / DD);
    float rstd = rsqrtf(var + 1e-5f);
    float* o = out + (long)row * DD;
    #pragma unroll
    for (int i = 0; i < 3; i++) {
        int c = tid + 256 * i;
        o[c] = (v[i] - mean) * rstd * g[c] + bb[c];
    }
}

// ---------------- final: LN + linear(2) + softmax + argmax ------------------
__global__ __launch_bounds__(256)
void final_k(const float* __restrict__ X, const float* __restrict__ g,
             const float* __restrict__ bb, const float* __restrict__ lw,
             const float* __restrict__ lb, float* __restrict__ probs,
             float* __restrict__ path, int write_path) {
    __shared__ float red[32];
    int row = blockIdx.x, tid = threadIdx.x;
    const float* x = X + (long)row * DD;
    float v[3];
    float s = 0.f;
    #pragma unroll
    for (int i = 0; i < 3; i++) { v[i] = x[tid + 256 * i]; s += v[i]; }
    float mean = block_reduce_sum(s, red) * (1.f / DD);
    float vs = 0.f;
    #pragma unroll
    for (int i = 0; i < 3; i++) { float d = v[i] - mean; vs += d * d; }
    float var = block_reduce_sum(vs, red) * (1.f / DD);
    float rstd = rsqrtf(var + 1e-5f);
    float l0 = 0.f, l1 = 0.f;
    #pragma unroll
    for (int i = 0; i < 3; i++) {
        int c = tid + 256 * i;
        float yv = (v[i] - mean) * rstd * g[c] + bb[c];
        l0 += yv * lw[2 * c + 0];
        l1 += yv * lw[2 * c + 1];
    }
    l0 = block_reduce_sum(l0, red);
    l1 = block_reduce_sum(l1, red);
    if (tid == 0) {
        l0 += lb[0]; l1 += lb[1];
        float m = fmaxf(l0, l1);
        float e0 = expf(l0 - m), e1 = expf(l1 - m);
        float inv = 1.f / (e0 + e1);
        probs[2 * row + 0] = e0 * inv;
        probs[2 * row + 1] = e1 * inv;
        if (write_path) path[row] = (l1 > l0) ? 1.f : 0.f;
    }
}

// ---------------- launch -----------------------------------------------------
extern "C" void kernel_launch(void* const* d_in, const int* in_sizes, int n_in,
                              void* d_out, int out_size) {
    const float* ob  = (const float*)d_in[0];
    const int*   wi  = (const int*)d_in[1];
    const float* Wq  = (const float*)d_in[2];   const float* bq  = (const float*)d_in[3];
    const float* Wk  = (const float*)d_in[4];   const float* bk  = (const float*)d_in[5];
    const float* Wv  = (const float*)d_in[6];   const float* bv  = (const float*)d_in[7];
    const float* Wo  = (const float*)d_in[8];   const float* bo  = (const float*)d_in[9];
    const float* l1g = (const float*)d_in[10];  const float* l1b = (const float*)d_in[11];
    const float* W1f = (const float*)d_in[12];  const float* b1f = (const float*)d_in[13];
    const float* W2f = (const float*)d_in[14];  const float* b2f = (const float*)d_in[15];
    const float* l2g = (const float*)d_in[16];  const float* l2b = (const float*)d_in[17];
    const float* ng  = (const float*)d_in[18];  const float* nb  = (const float*)d_in[19];
    const float* lw  = (const float*)d_in[20];  const float* lb  = (const float*)d_in[21];

    float *feat, *q, *k, *v, *ctx, *tmp, *x, *x2, *ff1;
    __half *aexp, *wqx, *wkx, *wvx, *wox, *w1x, *w2x;
    int* first;
    cudaGetSymbolAddress((void**)&feat, g_feat);
    cudaGetSymbolAddress((void**)&q,    g_q);
    cudaGetSymbolAddress((void**)&k,    g_k);
    cudaGetSymbolAddress((void**)&v,    g_v);
    cudaGetSymbolAddress((void**)&ctx,  g_ctx);
    cudaGetSymbolAddress((void**)&tmp,  g_tmp);
    cudaGetSymbolAddress((void**)&x,    g_x);
    cudaGetSymbolAddress((void**)&x2,   g_x2);
    cudaGetSymbolAddress((void**)&ff1,  g_ff1);
    cudaGetSymbolAddress((void**)&aexp, g_aexp);
    cudaGetSymbolAddress((void**)&wqx,  g_wq);
    cudaGetSymbolAddress((void**)&wkx,  g_wk);
    cudaGetSymbolAddress((void**)&wvx,  g_wv);
    cudaGetSymbolAddress((void**)&wox,  g_wo);
    cudaGetSymbolAddress((void**)&w1x,  g_w1);
    cudaGetSymbolAddress((void**)&w2x,  g_w2);
    cudaGetSymbolAddress((void**)&first, g_first);

    cudaFuncSetAttribute(attn_k, cudaFuncAttributeMaxDynamicSharedMemorySize, ATTN_SMEM);
    cudaFuncSetAttribute(gemm_f16_k, cudaFuncAttributeMaxDynamicSharedMemorySize, GEMM_SMEM);

    // 1: fused weight prep (transpose + fp16 hi/lo split)
    prep_weights_k<<<dim3(DFF/32, DFF/32, 6), 256>>>(Wq, Wk, Wv, Wo, W1f, W2f,
                                                     wqx, wkx, wvx, wox, w1x, w2x);
    // 2-4: gather
    init_first_k<<<(BW + 255) / 256, 256>>>(first);
    scan_first_k<<<(BSZ * TT + 255) / 256, 256>>>(wi, first);
    gather_k<<<BW, 192>>>(ob, first, feat);

    // 5: split feat; 6: gemm Q  <-- launch #6 gets profiled
    dim3 gDD(3, 128), gFF(12, 128);
    split_a_k<<<dim3(DD/256, BW), 256>>>(feat, aexp, DD);
    gemm_f16_k<<<gDD, 256, GEMM_SMEM>>>(aexp, wqx, bq, q, BW, DD, DD, 0);
    gemm_f16_k<<<gDD, 256, GEMM_SMEM>>>(aexp, wkx, bk, k, BW, DD, DD, 0);
    gemm_f16_k<<<gDD, 256, GEMM_SMEM>>>(aexp, wvx, bv, v, BW, DD, DD, 0);

    // attention
    attn_k<<<BSZ * HH, 256, ATTN_SMEM>>>(q, k, v, ctx);

    // output proj + LN1
    split_a_k<<<dim3(DD/256, BW), 256>>>(ctx, aexp, DD);
    gemm_f16_k<<<gDD, 256, GEMM_SMEM>>>(aexp, wox, bo, tmp, BW, DD, DD, 0);
    add_ln_k<<<BW, 256>>>(feat, tmp, l1g, l1b, x);

    // FFN + LN2
    split_a_k<<<dim3(DD/256, BW), 256>>>(x, aexp, DD);
    gemm_f16_k<<<gFF, 256, GEMM_SMEM>>>(aexp, w1x, b1f, ff1, BW, DFF, DD, 1);
    split_a_k<<<dim3(DFF/256, BW), 256>>>(ff1, aexp, DFF);
    gemm_f16_k<<<gDD, 256, GEMM_SMEM>>>(aexp, w2x, b2f, tmp, BW, DD, DFF, 0);
    add_ln_k<<<BW, 256>>>(x, tmp, l2g, l2b, x2);

    // final LN + linear + softmax + argmax
    float* probs = (float*)d_out;
    float* path  = probs + (long)BW * 2;
    int wp = (out_size >= BW * 3) ? 1 : 0;
    final_k<<<BW, 256>>>(x2, ng, nb, lw, lb, probs, path, wp);
}

// round 5
// speedup vs baseline: 1.7963x; 1.0298x over previous
#include <cuda_runtime.h>
#include <cuda_fp16.h>
#include <math.h>
#include <stdint.h>

#define BSZ 64
#define TT  512
#define DD  768
#define WW  255
#define HH  8
#define DHD 96
#define BW  (BSZ*WW)      // 16320
#define DFF 3072

// ---------------- scratch (device globals; no allocation allowed) ----------
static __device__ float  g_feat[BW*DD];
static __device__ float  g_q[BW*DD];
static __device__ float  g_k[BW*DD];
static __device__ float  g_v[BW*DD];
static __device__ float  g_tmp[BW*DD];
static __device__ float  g_x[BW*DD];
static __device__ float  g_x2[BW*DD];
static __device__ __half g_aexpA[(long)BW*2*DD];     // [M, 1536] halfs
static __device__ __half g_aexpB[(long)BW*2*DFF];    // [M, 6144] halfs
static __device__ __half g_wq[DD*2*DD];
static __device__ __half g_wk[DD*2*DD];
static __device__ __half g_wv[DD*2*DD];
static __device__ __half g_wo[DD*2*DD];
static __device__ __half g_w1[DFF*2*DD];             // [3072][1536]
static __device__ __half g_w2[DD*2*DFF];             // [768][6144]

// ---------------- helpers ----------------------------------------------------
#define CP16(d,s)  asm volatile("cp.async.cg.shared.global [%0], [%1], 16;" :: "r"(d), "l"(s))
#define CPCOMMIT() asm volatile("cp.async.commit_group;" ::: "memory")
#define CPWAIT1()  asm volatile("cp.async.wait_group 1;" ::: "memory")

#define LDSM4(r0,r1,r2,r3,addr) \
    asm volatile("ldmatrix.sync.aligned.m8n8.x4.shared.b16 {%0,%1,%2,%3}, [%4];" \
        : "=r"(r0), "=r"(r1), "=r"(r2), "=r"(r3) : "r"(addr))

__device__ __forceinline__ uint32_t smem_u32(const void* p){
    uint32_t a;
    asm("{ .reg .u64 t; cvta.to.shared.u64 t, %1; cvt.u32.u64 %0, t; }" : "=r"(a) : "l"(p));
    return a;
}

__device__ __forceinline__ void mma_f16(float* c, const uint32_t* a, const uint32_t* b){
    asm volatile(
        "mma.sync.aligned.m16n8k16.row.col.f32.f16.f16.f32 "
        "{%0,%1,%2,%3}, {%4,%5,%6,%7}, {%8,%9}, {%0,%1,%2,%3};"
        : "+f"(c[0]), "+f"(c[1]), "+f"(c[2]), "+f"(c[3])
        : "r"(a[0]), "r"(a[1]), "r"(a[2]), "r"(a[3]), "r"(b[0]), "r"(b[1]));
}

__device__ __forceinline__ void split2(float v, __half& h, __half& l){
    h = __float2half_rn(v);
    l = __float2half_rn(v - __half2float(h));
}

// ---------------- fused weight prep: transpose + fp16 hi/lo split -----------
__global__ void prep_weights_k(
    const float* __restrict__ Wq, const float* __restrict__ Wk,
    const float* __restrict__ Wv, const float* __restrict__ Wo,
    const float* __restrict__ W1, const float* __restrict__ W2,
    __half* wq, __half* wk, __half* wv, __half* wo, __half* w1, __half* w2)
{
    __shared__ float t[32][33];
    int z = blockIdx.z;
    const float* W; __half* Bx; int K, N;
    switch (z) {
        case 0: W = Wq; Bx = wq; K = DD;  N = DD;  break;
        case 1: W = Wk; Bx = wk; K = DD;  N = DD;  break;
        case 2: W = Wv; Bx = wv; K = DD;  N = DD;  break;
        case 3: W = Wo; Bx = wo; K = DD;  N = DD;  break;
        case 4: W = W1; Bx = w1; K = DD;  N = DFF; break;
        default:W = W2; Bx = w2; K = DFF; N = DD;  break;
    }
    int n0 = blockIdx.x * 32, k0 = blockIdx.y * 32;
    if (n0 >= N || k0 >= K) return;
    int tx = threadIdx.x & 31, ty = threadIdx.x >> 5;
    #pragma unroll
    for (int r = ty; r < 32; r += 8)
        t[r][tx] = W[(long)(k0 + r) * N + n0 + tx];
    __syncthreads();
    #pragma unroll
    for (int r = ty; r < 32; r += 8) {
        float v = t[tx][r];               // = W[k0+tx][n0+r]
        __half h, l; split2(v, h, l);
        long b = (long)(n0 + r) * (2 * K) + k0 + tx;
        Bx[b] = h;
        Bx[b + K] = l;
    }
}

// ---------------- fused gather: first-subtoken + copy + split ---------------
__global__ __launch_bounds__(256)
void gather_fused_k(const float* __restrict__ ob, const int* __restrict__ wi,
                    float* __restrict__ feat, __half* __restrict__ aexpA) {
    __shared__ int first[WW];
    int b = blockIdx.x, tid = threadIdx.x;
    for (int i = tid; i < WW; i += 256) first[i] = TT;
    __syncthreads();
    for (int t = tid; t < TT; t += 256) {
        int w = wi[b * TT + t];
        if (w >= 0 && w < WW) atomicMin(&first[w], t);
    }
    __syncthreads();
    for (int idx = tid; idx < WW * 192; idx += 256) {
        int row = idx / 192, c4 = idx % 192;
        int t = first[row]; if (t >= TT) t = 0;
        float4 val = ((const float4*)(ob + ((long)(b * TT + t)) * DD))[c4];
        long gr = (long)b * WW + row;
        ((float4*)(feat + gr * DD))[c4] = val;
        float vv[4] = {val.x, val.y, val.z, val.w};
        __half hs[4], ls[4];
        #pragma unroll
        for (int j = 0; j < 4; j++) split2(vv[j], hs[j], ls[j]);
        __half2* ph = (__half2*)(aexpA + gr * 1536 + c4 * 4);
        ph[0] = __halves2half2(hs[0], hs[1]);
        ph[1] = __halves2half2(hs[2], hs[3]);
        __half2* pl = (__half2*)(aexpA + gr * 1536 + 768 + c4 * 4);
        pl[0] = __halves2half2(ls[0], ls[1]);
        pl[1] = __halves2half2(ls[2], ls[3]);
    }
}

// ---------------- fp16x3 GEMM with ldmatrix ---------------------------------
// A2 = [Ah|Al] halfs [M, 2K]; B2 = [Bh|Bl] halfs [N, 2K].
// C = Ah*Bh + Ah*Bl + Al*Bh (fp32 accum). CTA 128x256, warp 64x64, 8 warps.
#define KT 64
#define SH 72
#define A_HALFS (128*SH)
#define B_HALFS (256*SH)
#define STG_HALFS (2*A_HALFS + 2*B_HALFS)
#define STG_BYTES (STG_HALFS*2)
#define GEMM_SMEM (2*STG_BYTES)

__global__ __launch_bounds__(256)
void gemm_f16_k(const __half* __restrict__ A2, const __half* __restrict__ B2,
                const float* __restrict__ bias, float* __restrict__ C,
                __half* __restrict__ Csplit, int M, int N, int K, int relu)
{
    extern __shared__ __half smh[];
    uint32_t sb = smem_u32(smh);
    int tid = threadIdx.x, wid = tid >> 5, lane = tid & 31;
    int g = lane >> 2, tg = lane & 3;
    int wm = wid & 1, wn = wid >> 1;
    const int K2 = 2 * K;
    const int S = K / KT;
    const long mrow0 = (long)blockIdx.y * 128;
    const long nrow0 = (long)blockIdx.x * 256;

    // ldmatrix per-thread byte offsets within A / B regions
    uint32_t aOff[4], bOff[4];
    {
        int r = wm * 64 + (lane & 15);
        int kc = (lane >> 4) * 8;
        #pragma unroll
        for (int mf = 0; mf < 4; mf++)
            aOff[mf] = (uint32_t)((r + mf * 16) * (SH * 2) + kc * 2);
        int q = lane >> 3, rl = lane & 7;
        int nn = wn * 64 + ((q >> 1) * 8) + rl;
        int kk = (q & 1) * 8;
        #pragma unroll
        for (int p = 0; p < 4; p++)
            bOff[p] = (uint32_t)((nn + p * 16) * (SH * 2) + kk * 2);
    }

    float acc[4][8][4];
    #pragma unroll
    for (int i = 0; i < 4; i++)
        #pragma unroll
        for (int j = 0; j < 8; j++)
            #pragma unroll
            for (int r = 0; r < 4; r++) acc[i][j][r] = 0.f;

    #define LOAD_STAGE(ks, slot) do { \
        uint32_t base_ = sb + (slot) * STG_BYTES; \
        _Pragma("unroll") \
        for (int i_ = 0; i_ < 4; i_++) { \
            int c_ = i_ * 256 + tid; int r_ = c_ >> 3, q_ = c_ & 7; \
            long grow_ = mrow0 + r_; if (grow_ >= M) grow_ = M - 1; \
            const __half* s_ = A2 + grow_ * K2 + (ks) * KT + q_ * 8; \
            uint32_t d_ = base_ + (uint32_t)(r_ * (SH*2) + q_ * 16); \
            CP16(d_, s_); \
            CP16(d_ + A_HALFS*2, s_ + K); \
        } \
        _Pragma("unroll") \
        for (int i_ = 0; i_ < 8; i_++) { \
            int c_ = i_ * 256 + tid; int r_ = c_ >> 3, q_ = c_ & 7; \
            const __half* s_ = B2 + (long)(nrow0 + r_) * K2 + (ks) * KT + q_ * 8; \
            uint32_t d_ = base_ + (uint32_t)(2*A_HALFS*2 + r_ * (SH*2) + q_ * 16); \
            CP16(d_, s_); \
            CP16(d_ + B_HALFS*2, s_ + K); \
        } \
    } while (0)

    LOAD_STAGE(0, 0); CPCOMMIT();

    for (int it = 0; it < S; it++) {
        int slot = it & 1;
        if (it + 1 < S) { LOAD_STAGE(it + 1, (it + 1) & 1); }
        CPCOMMIT();
        CPWAIT1();
        __syncthreads();

        uint32_t stAh = sb + slot * STG_BYTES;
        uint32_t stAl = stAh + A_HALFS * 2;
        uint32_t stBh = stAh + 2 * A_HALFS * 2;
        uint32_t stBl = stBh + B_HALFS * 2;

        #pragma unroll
        for (int ks = 0; ks < 4; ks++) {
            uint32_t kb = (uint32_t)(ks * 32);   // 16 halfs = 32 bytes
            uint32_t a[4][4], bh[4][4], bl[4][4];
            #pragma unroll
            for (int mf = 0; mf < 4; mf++)
                LDSM4(a[mf][0], a[mf][1], a[mf][2], a[mf][3], stAh + aOff[mf] + kb);
            #pragma unroll
            for (int p = 0; p < 4; p++)
                LDSM4(bh[p][0], bh[p][1], bh[p][2], bh[p][3], stBh + bOff[p] + kb);
            #pragma unroll
            for (int p = 0; p < 4; p++)
                LDSM4(bl[p][0], bl[p][1], bl[p][2], bl[p][3], stBl + bOff[p] + kb);

            #pragma unroll
            for (int mf = 0; mf < 4; mf++)
                #pragma unroll
                for (int p = 0; p < 4; p++) {
                    mma_f16(acc[mf][2*p],   a[mf], &bh[p][0]);
                    mma_f16(acc[mf][2*p+1], a[mf], &bh[p][2]);
                    mma_f16(acc[mf][2*p],   a[mf], &bl[p][0]);
                    mma_f16(acc[mf][2*p+1], a[mf], &bl[p][2]);
                }
            // third product: Al * Bh
            #pragma unroll
            for (int mf = 0; mf < 4; mf++)
                LDSM4(a[mf][0], a[mf][1], a[mf][2], a[mf][3], stAl + aOff[mf] + kb);
            #pragma unroll
            for (int mf = 0; mf < 4; mf++)
                #pragma unroll
                for (int p = 0; p < 4; p++) {
                    mma_f16(acc[mf][2*p],   a[mf], &bh[p][0]);
                    mma_f16(acc[mf][2*p+1], a[mf], &bh[p][2]);
                }
        }
        __syncthreads();
    }

    // epilogue
    #pragma unroll
    for (int mf = 0; mf < 4; mf++) {
        long r0 = mrow0 + wm * 64 + mf * 16 + g;
        long r1 = r0 + 8;
        #pragma unroll
        for (int nf = 0; nf < 8; nf++) {
            long col = nrow0 + wn * 64 + nf * 8 + 2 * tg;
            float b0 = bias[col], b1 = bias[col + 1];
            float v0 = acc[mf][nf][0] + b0, v1 = acc[mf][nf][1] + b1;
            float v2 = acc[mf][nf][2] + b0, v3 = acc[mf][nf][3] + b1;
            if (relu) {
                v0 = fmaxf(v0, 0.f); v1 = fmaxf(v1, 0.f);
                v2 = fmaxf(v2, 0.f); v3 = fmaxf(v3, 0.f);
            }
            if (Csplit) {
                __half h0, l0, h1, l1;
                if (r0 < M) {
                    split2(v0, h0, l0); split2(v1, h1, l1);
                    *(__half2*)&Csplit[r0 * (2*(long)N) + col]     = __halves2half2(h0, h1);
                    *(__half2*)&Csplit[r0 * (2*(long)N) + N + col] = __halves2half2(l0, l1);
                }
                if (r1 < M) {
                    split2(v2, h0, l0); split2(v3, h1, l1);
                    *(__half2*)&Csplit[r1 * (2*(long)N) + col]     = __halves2half2(h0, h1);
                    *(__half2*)&Csplit[r1 * (2*(long)N) + N + col] = __halves2half2(l0, l1);
                }
            } else {
                if (r0 < M) *(float2*)&C[r0 * N + col] = make_float2(v0, v1);
                if (r1 < M) *(float2*)&C[r1 * N + col] = make_float2(v2, v3);
            }
        }
    }
}

// ---------------- fused attention: one block per (b,h), split ctx out -------
#define KPAD 97
#define ATTN_SMEM ((2*WW*KPAD + 8*DHD + 8*256) * 4)

__global__ __launch_bounds__(256)
void attn_k(const float* __restrict__ q, const float* __restrict__ k,
            const float* __restrict__ v, __half* __restrict__ ctx_split) {
    int b = blockIdx.x / HH, h = blockIdx.x % HH;
    extern __shared__ float smfa[];
    float* ks = smfa;
    float* vs = ks + WW * KPAD;
    float* qs = vs + WW * KPAD;
    float* ps = qs + 8 * DHD;
    int tid = threadIdx.x, warp = tid >> 5, lane = tid & 31;

    for (int idx = tid; idx < WW * DHD; idx += 256) {
        int key = idx / DHD, d = idx % DHD;
        long gg = ((long)(b * WW + key)) * DD + h * DHD + d;
        ks[key * KPAD + d] = k[gg];
        vs[key * KPAD + d] = v[gg];
    }
    __syncthreads();

    const float scale = 0.10206207261596575f;

    for (int row0 = 0; row0 < WW; row0 += 8) {
        int row = row0 + warp;
        if (row < WW) {
            for (int d = lane; d < DHD; d += 32)
                qs[warp * DHD + d] = q[((long)(b * WW + row)) * DD + h * DHD + d];
        }
        __syncwarp();
        if (row < WW) {
            float sc[8];
            float m = -1e30f;
            #pragma unroll
            for (int kk = 0; kk < 8; kk++) {
                int key = lane + kk * 32;
                float s = -1e30f;
                if (key < WW) {
                    s = 0.f;
                    #pragma unroll 8
                    for (int d = 0; d < DHD; d++)
                        s += qs[warp * DHD + d] * ks[key * KPAD + d];
                    s *= scale;
                }
                sc[kk] = s;
                m = fmaxf(m, s);
            }
            #pragma unroll
            for (int o = 16; o; o >>= 1) m = fmaxf(m, __shfl_xor_sync(0xffffffffu, m, o));
            float sum = 0.f;
            #pragma unroll
            for (int kk = 0; kk < 8; kk++) {
                float e = (sc[kk] > -1e29f) ? __expf(sc[kk] - m) : 0.f;
                sc[kk] = e; sum += e;
            }
            #pragma unroll
            for (int o = 16; o; o >>= 1) sum += __shfl_xor_sync(0xffffffffu, sum, o);
            float inv = 1.f / sum;
            #pragma unroll
            for (int kk = 0; kk < 8; kk++) {
                int key = lane + kk * 32;
                if (key < 256) ps[warp * 256 + key] = sc[kk] * inv;
            }
        }
        __syncwarp();
        if (row < WW) {
            int d0 = lane * 3;
            float a0 = 0.f, a1 = 0.f, a2 = 0.f;
            for (int key = 0; key < WW; key++) {
                float p = ps[warp * 256 + key];
                const float* vr = &vs[key * KPAD + d0];
                a0 += p * vr[0];
                a1 += p * vr[1];
                a2 += p * vr[2];
            }
            long base = ((long)(b * WW + row)) * 1536 + h * DHD + d0;
            __half h0, l0;
            split2(a0, h0, l0); ctx_split[base + 0] = h0; ctx_split[base + 768 + 0] = l0;
            split2(a1, h0, l0); ctx_split[base + 1] = h0; ctx_split[base + 768 + 1] = l0;
            split2(a2, h0, l0); ctx_split[base + 2] = h0; ctx_split[base + 768 + 2] = l0;
        }
        __syncwarp();
    }
}

// ---------------- block reduce helper ---------------------------------------
__device__ __forceinline__ float block_reduce_sum(float val, float* red) {
    int lane = threadIdx.x & 31, warp = threadIdx.x >> 5;
    #pragma unroll
    for (int o = 16; o; o >>= 1) val += __shfl_xor_sync(0xffffffffu, val, o);
    if (lane == 0) red[warp] = val;
    __syncthreads();
    if (warp == 0) {
        float v = (lane < 8) ? red[lane] : 0.f;
        #pragma unroll
        for (int o = 4; o; o >>= 1) v += __shfl_xor_sync(0xffffffffu, v, o);
        if (lane == 0) red[0] = v;
    }
    __syncthreads();
    float r = red[0];
    __syncthreads();
    return r;
}

// ---------------- residual add + layernorm (+ optional split out) -----------
__global__ __launch_bounds__(256)
void add_ln_k(const float* __restrict__ X, const float* __restrict__ Y,
              const float* __restrict__ g, const float* __restrict__ bb,
              float* __restrict__ out, __half* __restrict__ split) {
    __shared__ float red[32];
    int row = blockIdx.x, tid = threadIdx.x;
    const float* x = X + (long)row * DD;
    const float* y = Y + (long)row * DD;
    float v[3];
    float s = 0.f;
    #pragma unroll
    for (int i = 0; i < 3; i++) {
        int c = tid + 256 * i;
        v[i] = x[c] + y[c];
        s += v[i];
    }
    float mean = block_reduce_sum(s, red) * (1.f / DD);
    float vs = 0.f;
    #pragma unroll
    for (int i = 0; i < 3; i++) { float d = v[i] - mean; vs += d * d; }
    float var = block_reduce_sum(vs, red) * (1.f / DD);
    float rstd = rsqrtf(var + 1e-5f);
    float* o = out + (long)row * DD;
    #pragma unroll
    for (int i = 0; i < 3; i++) {
        int c = tid + 256 * i;
        float val = (v[i] - mean) * rstd * g[c] + bb[c];
        o[c] = val;
        if (split) {
            __half h, l; split2(val, h, l);
            split[(long)row * 1536 + c] = h;
            split[(long)row * 1536 + 768 + c] = l;
        }
    }
}

// ---------------- final: LN + linear(2) + softmax + argmax ------------------
__global__ __launch_bounds__(256)
void final_k(const float* __restrict__ X, const float* __restrict__ g,
             const float* __restrict__ bb, const float* __restrict__ lw,
             const float* __restrict__ lb, float* __restrict__ probs,
             float* __restrict__ path, int write_path) {
    __shared__ float red[32];
    int row = blockIdx.x, tid = threadIdx.x;
    const float* x = X + (long)row * DD;
    float v[3];
    float s = 0.f;
    #pragma unroll
    for (int i = 0; i < 3; i++) { v[i] = x[tid + 256 * i]; s += v[i]; }
    float mean = block_reduce_sum(s, red) * (1.f / DD);
    float vs = 0.f;
    #pragma unroll
    for (int i = 0; i < 3; i++) { float d = v[i] - mean; vs += d * d; }
    float var = block_reduce_sum(vs, red) * (1.f / DD);
    float rstd = rsqrtf(var + 1e-5f);
    float l0 = 0.f, l1 = 0.f;
    #pragma unroll
    for (int i = 0; i < 3; i++) {
        int c = tid + 256 * i;
        float yv = (v[i] - mean) * rstd * g[c] + bb[c];
        l0 += yv * lw[2 * c + 0];
        l1 += yv * lw[2 * c + 1];
    }
    l0 = block_reduce_sum(l0, red);
    l1 = block_reduce_sum(l1, red);
    if (tid == 0) {
        l0 += lb[0]; l1 += lb[1];
        float m = fmaxf(l0, l1);
        float e0 = expf(l0 - m), e1 = expf(l1 - m);
        float inv = 1.f / (e0 + e1);
        probs[2 * row + 0] = e0 * inv;
        probs[2 * row + 1] = e1 * inv;
        if (write_path) path[row] = (l1 > l0) ? 1.f : 0.f;
    }
}

// ---------------- launch -----------------------------------------------------
extern "C" void kernel_launch(void* const* d_in, const int* in_sizes, int n_in,
                              void* d_out, int out_size) {
    const float* ob  = (const float*)d_in[0];
    const int*   wi  = (const int*)d_in[1];
    const float* Wq  = (const float*)d_in[2];   const float* bq  = (const float*)d_in[3];
    const float* Wk  = (const float*)d_in[4];   const float* bk  = (const float*)d_in[5];
    const float* Wv  = (const float*)d_in[6];   const float* bv  = (const float*)d_in[7];
    const float* Wo  = (const float*)d_in[8];   const float* bo  = (const float*)d_in[9];
    const float* l1g = (const float*)d_in[10];  const float* l1b = (const float*)d_in[11];
    const float* W1f = (const float*)d_in[12];  const float* b1f = (const float*)d_in[13];
    const float* W2f = (const float*)d_in[14];  const float* b2f = (const float*)d_in[15];
    const float* l2g = (const float*)d_in[16];  const float* l2b = (const float*)d_in[17];
    const float* ng  = (const float*)d_in[18];  const float* nb  = (const float*)d_in[19];
    const float* lw  = (const float*)d_in[20];  const float* lb  = (const float*)d_in[21];

    float *feat, *q, *k, *v, *tmp, *x, *x2;
    __half *aexpA, *aexpB, *wqx, *wkx, *wvx, *wox, *w1x, *w2x;
    cudaGetSymbolAddress((void**)&feat, g_feat);
    cudaGetSymbolAddress((void**)&q,    g_q);
    cudaGetSymbolAddress((void**)&k,    g_k);
    cudaGetSymbolAddress((void**)&v,    g_v);
    cudaGetSymbolAddress((void**)&tmp,  g_tmp);
    cudaGetSymbolAddress((void**)&x,    g_x);
    cudaGetSymbolAddress((void**)&x2,   g_x2);
    cudaGetSymbolAddress((void**)&aexpA, g_aexpA);
    cudaGetSymbolAddress((void**)&aexpB, g_aexpB);
    cudaGetSymbolAddress((void**)&wqx,  g_wq);
    cudaGetSymbolAddress((void**)&wkx,  g_wk);
    cudaGetSymbolAddress((void**)&wvx,  g_wv);
    cudaGetSymbolAddress((void**)&wox,  g_wo);
    cudaGetSymbolAddress((void**)&w1x,  g_w1);
    cudaGetSymbolAddress((void**)&w2x,  g_w2);

    cudaFuncSetAttribute(attn_k, cudaFuncAttributeMaxDynamicSharedMemorySize, ATTN_SMEM);
    cudaFuncSetAttribute(gemm_f16_k, cudaFuncAttributeMaxDynamicSharedMemorySize, GEMM_SMEM);

    // 1: weight prep
    prep_weights_k<<<dim3(DFF/32, DFF/32, 6), 256>>>(Wq, Wk, Wv, Wo, W1f, W2f,
                                                     wqx, wkx, wvx, wox, w1x, w2x);
    // 2: fused gather (+ feat split)
    gather_fused_k<<<BSZ, 256>>>(ob, wi, feat, aexpA);

    // 3-5: QKV projections
    dim3 gDD(3, 128), gFF(12, 128);
    gemm_f16_k<<<gDD, 256, GEMM_SMEM>>>(aexpA, wqx, bq, q, nullptr, BW, DD, DD, 0);
    gemm_f16_k<<<gDD, 256, GEMM_SMEM>>>(aexpA, wkx, bk, k, nullptr, BW, DD, DD, 0);
    gemm_f16_k<<<gDD, 256, GEMM_SMEM>>>(aexpA, wvx, bv, v, nullptr, BW, DD, DD, 0);

    // 6: attention (writes split ctx into aexpA)
    attn_k<<<BSZ * HH, 256, ATTN_SMEM>>>(q, k, v, aexpA);

    // 7: output proj + 8: LN1 (writes x + split into aexpA)
    gemm_f16_k<<<gDD, 256, GEMM_SMEM>>>(aexpA, wox, bo, tmp, nullptr, BW, DD, DD, 0);
    add_ln_k<<<BW, 256>>>(feat, tmp, l1g, l1b, x, aexpA);

    // 9: FFN1 (relu + split epilogue -> aexpB); 10: FFN2; 11: LN2
    gemm_f16_k<<<gFF, 256, GEMM_SMEM>>>(aexpA, w1x, b1f, nullptr, aexpB, BW, DFF, DD, 1);
    gemm_f16_k<<<gDD, 256, GEMM_SMEM>>>(aexpB, w2x, b2f, tmp, nullptr, BW, DD, DFF, 0);
    add_ln_k<<<BW, 256>>>(x, tmp, l2g, l2b, x2, nullptr);

    // 12: final LN + linear + softmax + argmax
    float* probs = (float*)d_out;
    float* path  = probs + (long)BW * 2;
    int wp = (out_size >= BW * 3) ? 1 : 0;
    final_k<<<BW, 256>>>(x2, ng, nb, lw, lb, probs, path, wp);
}

// round 6
// speedup vs baseline: 2.2837x; 1.2714x over previous
#include <cuda_runtime.h>
#include <cuda_fp16.h>
#include <math.h>
#include <stdint.h>

#define BSZ 64
#define TT  512
#define DD  768
#define WW  255
#define HH  8
#define DHD 96
#define BW  (BSZ*WW)      // 16320
#define DFF 3072

// ---------------- scratch (device globals; no allocation allowed) ----------
static __device__ float  g_feat[BW*DD];
static __device__ float  g_q[BW*DD];
static __device__ float  g_k[BW*DD];
static __device__ float  g_v[BW*DD];
static __device__ float  g_tmp[BW*DD];
static __device__ float  g_x[BW*DD];
static __device__ float  g_x2[BW*DD];
static __device__ __half g_aexpA[(long)BW*2*DD];     // [M, 1536] halfs
static __device__ __half g_aexpB[(long)BW*2*DFF];    // [M, 6144] halfs
static __device__ __half g_wq[DD*2*DD];
static __device__ __half g_wk[DD*2*DD];
static __device__ __half g_wv[DD*2*DD];
static __device__ __half g_wo[DD*2*DD];
static __device__ __half g_w1[DFF*2*DD];             // [3072][1536]
static __device__ __half g_w2[DD*2*DFF];             // [768][6144]

// ---------------- helpers ----------------------------------------------------
#define CP16(d,s)  asm volatile("cp.async.cg.shared.global [%0], [%1], 16;" :: "r"(d), "l"(s))
#define CPCOMMIT() asm volatile("cp.async.commit_group;" ::: "memory")
#define CPWAIT1()  asm volatile("cp.async.wait_group 1;" ::: "memory")

#define LDSM4(r0,r1,r2,r3,addr) \
    asm volatile("ldmatrix.sync.aligned.m8n8.x4.shared.b16 {%0,%1,%2,%3}, [%4];" \
        : "=r"(r0), "=r"(r1), "=r"(r2), "=r"(r3) : "r"(addr))

__device__ __forceinline__ uint32_t smem_u32(const void* p){
    uint32_t a;
    asm("{ .reg .u64 t; cvta.to.shared.u64 t, %1; cvt.u32.u64 %0, t; }" : "=r"(a) : "l"(p));
    return a;
}

__device__ __forceinline__ void mma_f16(float* c, const uint32_t* a, const uint32_t* b){
    asm volatile(
        "mma.sync.aligned.m16n8k16.row.col.f32.f16.f16.f32 "
        "{%0,%1,%2,%3}, {%4,%5,%6,%7}, {%8,%9}, {%0,%1,%2,%3};"
        : "+f"(c[0]), "+f"(c[1]), "+f"(c[2]), "+f"(c[3])
        : "r"(a[0]), "r"(a[1]), "r"(a[2]), "r"(a[3]), "r"(b[0]), "r"(b[1]));
}

__device__ __forceinline__ void split2(float v, __half& h, __half& l){
    h = __float2half_rn(v);
    l = __float2half_rn(v - __half2float(h));
}

// ---------------- fused weight prep: transpose + fp16 hi/lo split -----------
__global__ void prep_weights_k(
    const float* __restrict__ Wq, const float* __restrict__ Wk,
    const float* __restrict__ Wv, const float* __restrict__ Wo,
    const float* __restrict__ W1, const float* __restrict__ W2,
    __half* wq, __half* wk, __half* wv, __half* wo, __half* w1, __half* w2)
{
    __shared__ float t[32][33];
    int z = blockIdx.z;
    const float* W; __half* Bx; int K, N;
    switch (z) {
        case 0: W = Wq; Bx = wq; K = DD;  N = DD;  break;
        case 1: W = Wk; Bx = wk; K = DD;  N = DD;  break;
        case 2: W = Wv; Bx = wv; K = DD;  N = DD;  break;
        case 3: W = Wo; Bx = wo; K = DD;  N = DD;  break;
        case 4: W = W1; Bx = w1; K = DD;  N = DFF; break;
        default:W = W2; Bx = w2; K = DFF; N = DD;  break;
    }
    int n0 = blockIdx.x * 32, k0 = blockIdx.y * 32;
    if (n0 >= N || k0 >= K) return;
    int tx = threadIdx.x & 31, ty = threadIdx.x >> 5;
    #pragma unroll
    for (int r = ty; r < 32; r += 8)
        t[r][tx] = W[(long)(k0 + r) * N + n0 + tx];
    __syncthreads();
    #pragma unroll
    for (int r = ty; r < 32; r += 8) {
        float v = t[tx][r];
        __half h, l; split2(v, h, l);
        long b = (long)(n0 + r) * (2 * K) + k0 + tx;
        Bx[b] = h;
        Bx[b + K] = l;
    }
}

// ---------------- fused gather: first-subtoken + copy + split ---------------
__global__ __launch_bounds__(256)
void gather_fused_k(const float* __restrict__ ob, const int* __restrict__ wi,
                    float* __restrict__ feat, __half* __restrict__ aexpA) {
    __shared__ int first[WW];
    int b = blockIdx.x, tid = threadIdx.x;
    for (int i = tid; i < WW; i += 256) first[i] = TT;
    __syncthreads();
    for (int t = tid; t < TT; t += 256) {
        int w = wi[b * TT + t];
        if (w >= 0 && w < WW) atomicMin(&first[w], t);
    }
    __syncthreads();
    for (int idx = tid; idx < WW * 192; idx += 256) {
        int row = idx / 192, c4 = idx % 192;
        int t = first[row]; if (t >= TT) t = 0;
        float4 val = ((const float4*)(ob + ((long)(b * TT + t)) * DD))[c4];
        long gr = (long)b * WW + row;
        ((float4*)(feat + gr * DD))[c4] = val;
        float vv[4] = {val.x, val.y, val.z, val.w};
        __half hs[4], ls[4];
        #pragma unroll
        for (int j = 0; j < 4; j++) split2(vv[j], hs[j], ls[j]);
        __half2* ph = (__half2*)(aexpA + gr * 1536 + c4 * 4);
        ph[0] = __halves2half2(hs[0], hs[1]);
        ph[1] = __halves2half2(hs[2], hs[3]);
        __half2* pl = (__half2*)(aexpA + gr * 1536 + 768 + c4 * 4);
        pl[0] = __halves2half2(ls[0], ls[1]);
        pl[1] = __halves2half2(ls[2], ls[3]);
    }
}

// ---------------- fp16x3 GEMM with ldmatrix, RAW-distance-optimized ---------
#define KT 64
#define SH 72
#define A_HALFS (128*SH)
#define B_HALFS (256*SH)
#define STG_HALFS (2*A_HALFS + 2*B_HALFS)
#define STG_BYTES (STG_HALFS*2)
#define GEMM_SMEM (2*STG_BYTES)

__global__ __launch_bounds__(256)
void gemm_f16_k(const __half* __restrict__ A2, const __half* __restrict__ B2,
                const float* __restrict__ bias, float* __restrict__ C,
                __half* __restrict__ Csplit, int M, int N, int K, int relu)
{
    extern __shared__ __half smh[];
    uint32_t sb = smem_u32(smh);
    int tid = threadIdx.x, wid = tid >> 5, lane = tid & 31;
    int g = lane >> 2, tg = lane & 3;
    int wm = wid & 1, wn = wid >> 1;
    const int K2 = 2 * K;
    const int S = K / KT;
    const long mrow0 = (long)blockIdx.y * 128;
    const long nrow0 = (long)blockIdx.x * 256;

    uint32_t aOff[4], bOff[4];
    {
        int r = wm * 64 + (lane & 15);
        int kc = (lane >> 4) * 8;
        #pragma unroll
        for (int mf = 0; mf < 4; mf++)
            aOff[mf] = (uint32_t)((r + mf * 16) * (SH * 2) + kc * 2);
        int q = lane >> 3, rl = lane & 7;
        int nn = wn * 64 + ((q >> 1) * 8) + rl;
        int kk = (q & 1) * 8;
        #pragma unroll
        for (int p = 0; p < 4; p++)
            bOff[p] = (uint32_t)((nn + p * 16) * (SH * 2) + kk * 2);
    }

    float acc[4][8][4];
    #pragma unroll
    for (int i = 0; i < 4; i++)
        #pragma unroll
        for (int j = 0; j < 8; j++)
            #pragma unroll
            for (int r = 0; r < 4; r++) acc[i][j][r] = 0.f;

    #define LOAD_STAGE(ks, slot) do { \
        uint32_t base_ = sb + (slot) * STG_BYTES; \
        _Pragma("unroll") \
        for (int i_ = 0; i_ < 4; i_++) { \
            int c_ = i_ * 256 + tid; int r_ = c_ >> 3, q_ = c_ & 7; \
            long grow_ = mrow0 + r_; if (grow_ >= M) grow_ = M - 1; \
            const __half* s_ = A2 + grow_ * K2 + (ks) * KT + q_ * 8; \
            uint32_t d_ = base_ + (uint32_t)(r_ * (SH*2) + q_ * 16); \
            CP16(d_, s_); \
            CP16(d_ + A_HALFS*2, s_ + K); \
        } \
        _Pragma("unroll") \
        for (int i_ = 0; i_ < 8; i_++) { \
            int c_ = i_ * 256 + tid; int r_ = c_ >> 3, q_ = c_ & 7; \
            const __half* s_ = B2 + (long)(nrow0 + r_) * K2 + (ks) * KT + q_ * 8; \
            uint32_t d_ = base_ + (uint32_t)(2*A_HALFS*2 + r_ * (SH*2) + q_ * 16); \
            CP16(d_, s_); \
            CP16(d_ + B_HALFS*2, s_ + K); \
        } \
    } while (0)

    LOAD_STAGE(0, 0); CPCOMMIT();

    for (int it = 0; it < S; it++) {
        int slot = it & 1;
        if (it + 1 < S) { LOAD_STAGE(it + 1, (it + 1) & 1); }
        CPCOMMIT();
        CPWAIT1();
        __syncthreads();

        uint32_t stAh = sb + slot * STG_BYTES;
        uint32_t stAl = stAh + A_HALFS * 2;
        uint32_t stBh = stAh + 2 * A_HALFS * 2;
        uint32_t stBl = stBh + B_HALFS * 2;

        #pragma unroll
        for (int ks = 0; ks < 4; ks++) {
            uint32_t kb = (uint32_t)(ks * 32);
            uint32_t a[4][4], bh[4][4], bl[4][4];
            #pragma unroll
            for (int mf = 0; mf < 4; mf++)
                LDSM4(a[mf][0], a[mf][1], a[mf][2], a[mf][3], stAh + aOff[mf] + kb);
            #pragma unroll
            for (int p = 0; p < 4; p++)
                LDSM4(bh[p][0], bh[p][1], bh[p][2], bh[p][3], stBh + bOff[p] + kb);
            #pragma unroll
            for (int p = 0; p < 4; p++)
                LDSM4(bl[p][0], bl[p][1], bl[p][2], bl[p][3], stBl + bOff[p] + kb);

            // product 1: Ah*Bh (each acc touched once -> RAW distance 32)
            #pragma unroll
            for (int mf = 0; mf < 4; mf++)
                #pragma unroll
                for (int p = 0; p < 4; p++) {
                    mma_f16(acc[mf][2*p],   a[mf], &bh[p][0]);
                    mma_f16(acc[mf][2*p+1], a[mf], &bh[p][2]);
                }
            // product 2: Ah*Bl
            #pragma unroll
            for (int mf = 0; mf < 4; mf++)
                #pragma unroll
                for (int p = 0; p < 4; p++) {
                    mma_f16(acc[mf][2*p],   a[mf], &bl[p][0]);
                    mma_f16(acc[mf][2*p+1], a[mf], &bl[p][2]);
                }
            // reload A = Al
            #pragma unroll
            for (int mf = 0; mf < 4; mf++)
                LDSM4(a[mf][0], a[mf][1], a[mf][2], a[mf][3], stAl + aOff[mf] + kb);
            // product 3: Al*Bh
            #pragma unroll
            for (int mf = 0; mf < 4; mf++)
                #pragma unroll
                for (int p = 0; p < 4; p++) {
                    mma_f16(acc[mf][2*p],   a[mf], &bh[p][0]);
                    mma_f16(acc[mf][2*p+1], a[mf], &bh[p][2]);
                }
        }
        __syncthreads();
    }

    // epilogue
    #pragma unroll
    for (int mf = 0; mf < 4; mf++) {
        long r0 = mrow0 + wm * 64 + mf * 16 + g;
        long r1 = r0 + 8;
        #pragma unroll
        for (int nf = 0; nf < 8; nf++) {
            long col = nrow0 + wn * 64 + nf * 8 + 2 * tg;
            float b0 = bias[col], b1 = bias[col + 1];
            float v0 = acc[mf][nf][0] + b0, v1 = acc[mf][nf][1] + b1;
            float v2 = acc[mf][nf][2] + b0, v3 = acc[mf][nf][3] + b1;
            if (relu) {
                v0 = fmaxf(v0, 0.f); v1 = fmaxf(v1, 0.f);
                v2 = fmaxf(v2, 0.f); v3 = fmaxf(v3, 0.f);
            }
            if (Csplit) {
                __half h0, l0, h1, l1;
                if (r0 < M) {
                    split2(v0, h0, l0); split2(v1, h1, l1);
                    *(__half2*)&Csplit[r0 * (2*(long)N) + col]     = __halves2half2(h0, h1);
                    *(__half2*)&Csplit[r0 * (2*(long)N) + N + col] = __halves2half2(l0, l1);
                }
                if (r1 < M) {
                    split2(v2, h0, l0); split2(v3, h1, l1);
                    *(__half2*)&Csplit[r1 * (2*(long)N) + col]     = __halves2half2(h0, h1);
                    *(__half2*)&Csplit[r1 * (2*(long)N) + N + col] = __halves2half2(l0, l1);
                }
            } else {
                if (r0 < M) *(float2*)&C[r0 * N + col] = make_float2(v0, v1);
                if (r1 < M) *(float2*)&C[r1 * N + col] = make_float2(v2, v3);
            }
        }
    }
}

// ---------------- attention v2: register-tiled, d-major K -------------------
// smem: ks_t[96][255] fp32, vs[255][97] fp32, ps[32][256] fp32 (aliased w/ qs)
#define AT_KS   (96*WW)          // 24480 floats
#define AT_VS   (WW*97)          // 24735 floats
#define AT_PS   (32*256)         // 8192 floats
#define ATTN_SMEM ((AT_KS + AT_VS + AT_PS) * 4)   // 229,628 B

__global__ __launch_bounds__(256)
void attn2_k(const float* __restrict__ q, const float* __restrict__ k,
             const float* __restrict__ v, __half* __restrict__ ctx_split) {
    int b = blockIdx.x / HH, h = blockIdx.x % HH;
    extern __shared__ float smfa[];
    float* ks_t = smfa;               // [96][255] d-major
    float* vs   = ks_t + AT_KS;       // [255][97]
    float* ps   = vs + AT_VS;         // [32][256]
    float* qs   = ps;                 // alias: [32][96]
    int tid = threadIdx.x, warp = tid >> 5, lane = tid & 31;

    for (int idx = tid; idx < WW * DHD; idx += 256) {
        int key = idx / DHD, d = idx % DHD;
        long gg = ((long)(b * WW + key)) * DD + h * DHD + d;
        ks_t[d * WW + key] = k[gg];
        vs[key * 97 + d]   = v[gg];
    }
    __syncthreads();

    const float scale = 0.10206207261596575f;  // 1/sqrt(96)
    int d0 = lane * 3;

    for (int row0 = 0; row0 < 256; row0 += 32) {
        // load 32 q rows into qs (aliased with ps -- previous iter done via sync below)
        for (int idx = tid; idx < 32 * DHD; idx += 256) {
            int r = idx / DHD, d = idx % DHD;
            int row = row0 + r;
            qs[r * DHD + d] = (row < WW) ? q[((long)(b * WW + row)) * DD + h * DHD + d] : 0.f;
        }
        __syncthreads();

        // QK^T: warp owns 4 rows (local warp*4..+3), lane owns keys lane+32kk
        float sc[8][4];
        #pragma unroll
        for (int kk = 0; kk < 8; kk++)
            #pragma unroll
            for (int r = 0; r < 4; r++) sc[kk][r] = 0.f;

        const float* qr = &qs[(warp * 4) * DHD];
        for (int d = 0; d < DHD; d++) {
            float q0 = qr[d], q1 = qr[DHD + d], q2 = qr[2*DHD + d], q3 = qr[3*DHD + d];
            const float* kd = &ks_t[d * WW];
            #pragma unroll
            for (int kk = 0; kk < 8; kk++) {
                float kv = kd[lane + kk * 32];   // key 255 reads junk, masked later
                sc[kk][0] += kv * q0;
                sc[kk][1] += kv * q1;
                sc[kk][2] += kv * q2;
                sc[kk][3] += kv * q3;
            }
        }
        __syncthreads();   // all warps done reading qs; safe to overwrite with ps

        // softmax per row
        float inv[4], mx[4];
        #pragma unroll
        for (int r = 0; r < 4; r++) {
            float m = -1e30f;
            #pragma unroll
            for (int kk = 0; kk < 8; kk++) {
                int key = lane + kk * 32;
                float s = (key < WW) ? sc[kk][r] * scale : -1e30f;
                sc[kk][r] = s;
                m = fmaxf(m, s);
            }
            #pragma unroll
            for (int o = 16; o; o >>= 1) m = fmaxf(m, __shfl_xor_sync(0xffffffffu, m, o));
            mx[r] = m;
        }
        #pragma unroll
        for (int r = 0; r < 4; r++) {
            float sum = 0.f;
            #pragma unroll
            for (int kk = 0; kk < 8; kk++) {
                float e = (sc[kk][r] > -1e29f) ? __expf(sc[kk][r] - mx[r]) : 0.f;
                sc[kk][r] = e;
                sum += e;
            }
            #pragma unroll
            for (int o = 16; o; o >>= 1) sum += __shfl_xor_sync(0xffffffffu, sum, o);
            inv[r] = 1.f / sum;
        }
        #pragma unroll
        for (int r = 0; r < 4; r++)
            #pragma unroll
            for (int kk = 0; kk < 8; kk++)
                ps[(warp * 4 + r) * 256 + lane + kk * 32] = sc[kk][r] * inv[r];
        __syncwarp();

        // P@V: lane owns 3 d-columns, 4 rows
        float a0[3] = {0,0,0}, a1[3] = {0,0,0}, a2[3] = {0,0,0}, a3[3] = {0,0,0};
        const float* pr = &ps[(warp * 4) * 256];
        for (int key = 0; key < WW; key++) {
            float p0 = pr[key], p1 = pr[256 + key], p2 = pr[512 + key], p3 = pr[768 + key];
            const float* vr = &vs[key * 97 + d0];
            float vv0 = vr[0], vv1 = vr[1], vv2 = vr[2];
            a0[0] += p0*vv0; a0[1] += p0*vv1; a0[2] += p0*vv2;
            a1[0] += p1*vv0; a1[1] += p1*vv1; a1[2] += p1*vv2;
            a2[0] += p2*vv0; a2[1] += p2*vv1; a2[2] += p2*vv2;
            a3[0] += p3*vv0; a3[1] += p3*vv1; a3[2] += p3*vv2;
        }
        #pragma unroll
        for (int r = 0; r < 4; r++) {
            int row = row0 + warp * 4 + r;
            if (row < WW) {
                float* ar = (r == 0) ? a0 : (r == 1) ? a1 : (r == 2) ? a2 : a3;
                long base = ((long)(b * WW + row)) * 1536 + h * DHD + d0;
                #pragma unroll
                for (int j = 0; j < 3; j++) {
                    __half hh, ll; split2(ar[j], hh, ll);
                    ctx_split[base + j] = hh;
                    ctx_split[base + 768 + j] = ll;
                }
            }
        }
        __syncthreads();   // AV done before next iter overwrites qs/ps
    }
}

// ---------------- block reduce helper ---------------------------------------
__device__ __forceinline__ float block_reduce_sum(float val, float* red) {
    int lane = threadIdx.x & 31, warp = threadIdx.x >> 5;
    #pragma unroll
    for (int o = 16; o; o >>= 1) val += __shfl_xor_sync(0xffffffffu, val, o);
    if (lane == 0) red[warp] = val;
    __syncthreads();
    if (warp == 0) {
        float v = (lane < 8) ? red[lane] : 0.f;
        #pragma unroll
        for (int o = 4; o; o >>= 1) v += __shfl_xor_sync(0xffffffffu, v, o);
        if (lane == 0) red[0] = v;
    }
    __syncthreads();
    float r = red[0];
    __syncthreads();
    return r;
}

// ---------------- residual add + layernorm (+ optional split out) -----------
__global__ __launch_bounds__(256)
void add_ln_k(const float* __restrict__ X, const float* __restrict__ Y,
              const float* __restrict__ g, const float* __restrict__ bb,
              float* __restrict__ out, __half* __restrict__ split) {
    __shared__ float red[32];
    int row = blockIdx.x, tid = threadIdx.x;
    const float* x = X + (long)row * DD;
    const float* y = Y + (long)row * DD;
    float v[3];
    float s = 0.f;
    #pragma unroll
    for (int i = 0; i < 3; i++) {
        int c = tid + 256 * i;
        v[i] = x[c] + y[c];
        s += v[i];
    }
    float mean = block_reduce_sum(s, red) * (1.f / DD);
    float vs = 0.f;
    #pragma unroll
    for (int i = 0; i < 3; i++) { float d = v[i] - mean; vs += d * d; }
    float var = block_reduce_sum(vs, red) * (1.f / DD);
    float rstd = rsqrtf(var + 1e-5f);
    float* o = out + (long)row * DD;
    #pragma unroll
    for (int i = 0; i < 3; i++) {
        int c = tid + 256 * i;
        float val = (v[i] - mean) * rstd * g[c] + bb[c];
        o[c] = val;
        if (split) {
            __half h, l; split2(val, h, l);
            split[(long)row * 1536 + c] = h;
            split[(long)row * 1536 + 768 + c] = l;
        }
    }
}

// ---------------- final: LN + linear(2) + softmax + argmax ------------------
__global__ __launch_bounds__(256)
void final_k(const float* __restrict__ X, const float* __restrict__ g,
             const float* __restrict__ bb, const float* __restrict__ lw,
             const float* __restrict__ lb, float* __restrict__ probs,
             float* __restrict__ path, int write_path) {
    __shared__ float red[32];
    int row = blockIdx.x, tid = threadIdx.x;
    const float* x = X + (long)row * DD;
    float v[3];
    float s = 0.f;
    #pragma unroll
    for (int i = 0; i < 3; i++) { v[i] = x[tid + 256 * i]; s += v[i]; }
    float mean = block_reduce_sum(s, red) * (1.f / DD);
    float vs = 0.f;
    #pragma unroll
    for (int i = 0; i < 3; i++) { float d = v[i] - mean; vs += d * d; }
    float var = block_reduce_sum(vs, red) * (1.f / DD);
    float rstd = rsqrtf(var + 1e-5f);
    float l0 = 0.f, l1 = 0.f;
    #pragma unroll
    for (int i = 0; i < 3; i++) {
        int c = tid + 256 * i;
        float yv = (v[i] - mean) * rstd * g[c] + bb[c];
        l0 += yv * lw[2 * c + 0];
        l1 += yv * lw[2 * c + 1];
    }
    l0 = block_reduce_sum(l0, red);
    l1 = block_reduce_sum(l1, red);
    if (tid == 0) {
        l0 += lb[0]; l1 += lb[1];
        float m = fmaxf(l0, l1);
        float e0 = expf(l0 - m), e1 = expf(l1 - m);
        float inv = 1.f / (e0 + e1);
        probs[2 * row + 0] = e0 * inv;
        probs[2 * row + 1] = e1 * inv;
        if (write_path) path[row] = (l1 > l0) ? 1.f : 0.f;
    }
}

// ---------------- launch -----------------------------------------------------
extern "C" void kernel_launch(void* const* d_in, const int* in_sizes, int n_in,
                              void* d_out, int out_size) {
    const float* ob  = (const float*)d_in[0];
    const int*   wi  = (const int*)d_in[1];
    const float* Wq  = (const float*)d_in[2];   const float* bq  = (const float*)d_in[3];
    const float* Wk  = (const float*)d_in[4];   const float* bk  = (const float*)d_in[5];
    const float* Wv  = (const float*)d_in[6];   const float* bv  = (const float*)d_in[7];
    const float* Wo  = (const float*)d_in[8];   const float* bo  = (const float*)d_in[9];
    const float* l1g = (const float*)d_in[10];  const float* l1b = (const float*)d_in[11];
    const float* W1f = (const float*)d_in[12];  const float* b1f = (const float*)d_in[13];
    const float* W2f = (const float*)d_in[14];  const float* b2f = (const float*)d_in[15];
    const float* l2g = (const float*)d_in[16];  const float* l2b = (const float*)d_in[17];
    const float* ng  = (const float*)d_in[18];  const float* nb  = (const float*)d_in[19];
    const float* lw  = (const float*)d_in[20];  const float* lb  = (const float*)d_in[21];

    float *feat, *q, *k, *v, *tmp, *x, *x2;
    __half *aexpA, *aexpB, *wqx, *wkx, *wvx, *wox, *w1x, *w2x;
    cudaGetSymbolAddress((void**)&feat, g_feat);
    cudaGetSymbolAddress((void**)&q,    g_q);
    cudaGetSymbolAddress((void**)&k,    g_k);
    cudaGetSymbolAddress((void**)&v,    g_v);
    cudaGetSymbolAddress((void**)&tmp,  g_tmp);
    cudaGetSymbolAddress((void**)&x,    g_x);
    cudaGetSymbolAddress((void**)&x2,   g_x2);
    cudaGetSymbolAddress((void**)&aexpA, g_aexpA);
    cudaGetSymbolAddress((void**)&aexpB, g_aexpB);
    cudaGetSymbolAddress((void**)&wqx,  g_wq);
    cudaGetSymbolAddress((void**)&wkx,  g_wk);
    cudaGetSymbolAddress((void**)&wvx,  g_wv);
    cudaGetSymbolAddress((void**)&wox,  g_wo);
    cudaGetSymbolAddress((void**)&w1x,  g_w1);
    cudaGetSymbolAddress((void**)&w2x,  g_w2);

    cudaFuncSetAttribute(attn2_k, cudaFuncAttributeMaxDynamicSharedMemorySize, ATTN_SMEM);
    cudaFuncSetAttribute(gemm_f16_k, cudaFuncAttributeMaxDynamicSharedMemorySize, GEMM_SMEM);

    // 1: weight prep
    prep_weights_k<<<dim3(DFF/32, DFF/32, 6), 256>>>(Wq, Wk, Wv, Wo, W1f, W2f,
                                                     wqx, wkx, wvx, wox, w1x, w2x);
    // 2: fused gather (+ feat split)
    gather_fused_k<<<BSZ, 256>>>(ob, wi, feat, aexpA);

    // 3-5: QKV projections
    dim3 gDD(3, 128), gFF(12, 128);
    gemm_f16_k<<<gDD, 256, GEMM_SMEM>>>(aexpA, wqx, bq, q, nullptr, BW, DD, DD, 0);
    gemm_f16_k<<<gDD, 256, GEMM_SMEM>>>(aexpA, wkx, bk, k, nullptr, BW, DD, DD, 0);
    gemm_f16_k<<<gDD, 256, GEMM_SMEM>>>(aexpA, wvx, bv, v, nullptr, BW, DD, DD, 0);

    // 6: attention (writes split ctx into aexpA)
    attn2_k<<<BSZ * HH, 256, ATTN_SMEM>>>(q, k, v, aexpA);

    // 7: output proj + 8: LN1 (writes x + split into aexpA)
    gemm_f16_k<<<gDD, 256, GEMM_SMEM>>>(aexpA, wox, bo, tmp, nullptr, BW, DD, DD, 0);
    add_ln_k<<<BW, 256>>>(feat, tmp, l1g, l1b, x, aexpA);

    // 9: FFN1 (relu + split epilogue -> aexpB); 10: FFN2; 11: LN2
    gemm_f16_k<<<gFF, 256, GEMM_SMEM>>>(aexpA, w1x, b1f, nullptr, aexpB, BW, DFF, DD, 1);
    gemm_f16_k<<<gDD, 256, GEMM_SMEM>>>(aexpB, w2x, b2f, tmp, nullptr, BW, DD, DFF, 0);
    add_ln_k<<<BW, 256>>>(x, tmp, l2g, l2b, x2, nullptr);

    // 12: final LN + linear + softmax + argmax
    float* probs = (float*)d_out;
    float* path  = probs + (long)BW * 2;
    int wp = (out_size >= BW * 3) ? 1 : 0;
    final_k<<<BW, 256>>>(x2, ng, nb, lw, lb, probs, path, wp);
}

// round 7
// speedup vs baseline: 2.3591x; 1.0330x over previous
#include <cuda_runtime.h>
#include <cuda_fp16.h>
#include <math.h>
#include <stdint.h>

#define BSZ 64
#define TT  512
#define DD  768
#define WW  255
#define HH  8
#define DHD 96
#define BW  (BSZ*WW)      // 16320
#define DFF 3072
#define NQKV 2304

// ---------------- scratch (device globals; no allocation allowed) ----------
static __device__ float  g_feat[BW*DD];
static __device__ float  g_qkv[(long)BW*NQKV];
static __device__ float  g_tmp[BW*DD];
static __device__ float  g_tmp2[BW*DD];
static __device__ float  g_x[BW*DD];
static __device__ __half g_aexpA[(long)BW*2*DD];     // [M, 1536] halfs
static __device__ __half g_aexpB[(long)BW*2*DFF];    // [M, 6144] halfs
static __device__ __half g_wqkv[NQKV*2*DD];          // [2304][1536]
static __device__ __half g_wo[DD*2*DD];
static __device__ __half g_w1[DFF*2*DD];             // [3072][1536]
static __device__ __half g_w2[DD*2*DFF];             // [768][6144]
static __device__ float  g_bqkv[NQKV];

// ---------------- helpers ----------------------------------------------------
#define CP16(d,s)  asm volatile("cp.async.cg.shared.global [%0], [%1], 16;" :: "r"(d), "l"(s))
#define CPCOMMIT() asm volatile("cp.async.commit_group;" ::: "memory")
#define CPWAIT1()  asm volatile("cp.async.wait_group 1;" ::: "memory")

#define LDSM4(r0,r1,r2,r3,addr) \
    asm volatile("ldmatrix.sync.aligned.m8n8.x4.shared.b16 {%0,%1,%2,%3}, [%4];" \
        : "=r"(r0), "=r"(r1), "=r"(r2), "=r"(r3) : "r"(addr))

__device__ __forceinline__ uint32_t smem_u32(const void* p){
    uint32_t a;
    asm("{ .reg .u64 t; cvta.to.shared.u64 t, %1; cvt.u32.u64 %0, t; }" : "=r"(a) : "l"(p));
    return a;
}

__device__ __forceinline__ void mma_f16(float* c, const uint32_t* a, const uint32_t* b){
    asm volatile(
        "mma.sync.aligned.m16n8k16.row.col.f32.f16.f16.f32 "
        "{%0,%1,%2,%3}, {%4,%5,%6,%7}, {%8,%9}, {%0,%1,%2,%3};"
        : "+f"(c[0]), "+f"(c[1]), "+f"(c[2]), "+f"(c[3])
        : "r"(a[0]), "r"(a[1]), "r"(a[2]), "r"(a[3]), "r"(b[0]), "r"(b[1]));
}

__device__ __forceinline__ void split2(float v, __half& h, __half& l){
    h = __float2half_rn(v);
    l = __float2half_rn(v - __half2float(h));
}

// ---------------- fused weight prep: transpose + fp16 hi/lo split -----------
// Wq/Wk/Wv go into g_wqkv at row offsets 0/768/1536
__global__ void prep_weights_k(
    const float* __restrict__ Wq, const float* __restrict__ Wk,
    const float* __restrict__ Wv, const float* __restrict__ Wo,
    const float* __restrict__ W1, const float* __restrict__ W2,
    __half* wqkv, __half* wo, __half* w1, __half* w2)
{
    __shared__ float t[32][33];
    int z = blockIdx.z;
    const float* W; __half* Bx; int K, N;
    switch (z) {
        case 0: W = Wq; Bx = wqkv;                 K = DD;  N = DD;  break;
        case 1: W = Wk; Bx = wqkv + 768L*2*DD;     K = DD;  N = DD;  break;
        case 2: W = Wv; Bx = wqkv + 1536L*2*DD;    K = DD;  N = DD;  break;
        case 3: W = Wo; Bx = wo;                   K = DD;  N = DD;  break;
        case 4: W = W1; Bx = w1;                   K = DD;  N = DFF; break;
        default:W = W2; Bx = w2;                   K = DFF; N = DD;  break;
    }
    int n0 = blockIdx.x * 32, k0 = blockIdx.y * 32;
    if (n0 >= N || k0 >= K) return;
    int tx = threadIdx.x & 31, ty = threadIdx.x >> 5;
    #pragma unroll
    for (int r = ty; r < 32; r += 8)
        t[r][tx] = W[(long)(k0 + r) * N + n0 + tx];
    __syncthreads();
    #pragma unroll
    for (int r = ty; r < 32; r += 8) {
        float v = t[tx][r];
        __half h, l; split2(v, h, l);
        long b = (long)(n0 + r) * (2 * K) + k0 + tx;
        Bx[b] = h;
        Bx[b + K] = l;
    }
}

__global__ void concat_bias_k(const float* __restrict__ bq, const float* __restrict__ bk,
                              const float* __restrict__ bv, float* __restrict__ bqkv) {
    int i = blockIdx.x * 256 + threadIdx.x;
    if (i < DD) {
        bqkv[i] = bq[i];
        bqkv[DD + i] = bk[i];
        bqkv[2*DD + i] = bv[i];
    }
}

// ---------------- fused gather: first-subtoken + copy + split ---------------
__global__ __launch_bounds__(256)
void gather_fused_k(const float* __restrict__ ob, const int* __restrict__ wi,
                    float* __restrict__ feat, __half* __restrict__ aexpA) {
    __shared__ int first[WW];
    int b = blockIdx.x, tid = threadIdx.x;
    for (int i = tid; i < WW; i += 256) first[i] = TT;
    __syncthreads();
    for (int t = tid; t < TT; t += 256) {
        int w = wi[b * TT + t];
        if (w >= 0 && w < WW) atomicMin(&first[w], t);
    }
    __syncthreads();
    for (int idx = tid; idx < WW * 192; idx += 256) {
        int row = idx / 192, c4 = idx % 192;
        int t = first[row]; if (t >= TT) t = 0;
        float4 val = ((const float4*)(ob + ((long)(b * TT + t)) * DD))[c4];
        long gr = (long)b * WW + row;
        ((float4*)(feat + gr * DD))[c4] = val;
        float vv[4] = {val.x, val.y, val.z, val.w};
        __half hs[4], ls[4];
        #pragma unroll
        for (int j = 0; j < 4; j++) split2(vv[j], hs[j], ls[j]);
        __half2* ph = (__half2*)(aexpA + gr * 1536 + c4 * 4);
        ph[0] = __halves2half2(hs[0], hs[1]);
        ph[1] = __halves2half2(hs[2], hs[3]);
        __half2* pl = (__half2*)(aexpA + gr * 1536 + 768 + c4 * 4);
        pl[0] = __halves2half2(ls[0], ls[1]);
        pl[1] = __halves2half2(ls[2], ls[3]);
    }
}

// ---------------- fp16x3 GEMM, 512 threads, split-K via blockIdx.z ----------
#define KT 64
#define SH 72
#define A_HALFS (128*SH)
#define B_HALFS (256*SH)
#define STG_HALFS (2*A_HALFS + 2*B_HALFS)
#define STG_BYTES (STG_HALFS*2)          // 110592
#define GEMM_SMEM (2*STG_BYTES)          // 221184

__global__ __launch_bounds__(512)
void gemm_f16_k(const __half* __restrict__ A2, const __half* __restrict__ B2,
                const float* __restrict__ bias, float* __restrict__ C0,
                float* __restrict__ C1, __half* __restrict__ Csplit,
                int M, int N, int Kfull, int Keff, int relu)
{
    extern __shared__ __half smh[];
    uint32_t sb = smem_u32(smh);
    int tid = threadIdx.x, wid = tid >> 5, lane = tid & 31;
    int g = lane >> 2, tg = lane & 3;
    int wm = wid & 1, wn = wid >> 1;            // 2 x 8 warps, warp tile 64x32
    int z = blockIdx.z;
    int kbase = z * Keff;
    float* C = z ? C1 : C0;
    const float* bp = z ? nullptr : bias;
    const int K2 = 2 * Kfull;
    const int S = Keff / KT;
    const long mrow0 = (long)blockIdx.y * 128;
    const long nrow0 = (long)blockIdx.x * 256;

    uint32_t aOff[4], bOff[2];
    {
        int r = wm * 64 + (lane & 15);
        int kc = (lane >> 4) * 8;
        #pragma unroll
        for (int mf = 0; mf < 4; mf++)
            aOff[mf] = (uint32_t)((r + mf * 16) * (SH * 2) + kc * 2);
        int q = lane >> 3, rl = lane & 7;
        int nn = wn * 32 + ((q >> 1) * 8) + rl;
        int kk = (q & 1) * 8;
        #pragma unroll
        for (int p = 0; p < 2; p++)
            bOff[p] = (uint32_t)((nn + p * 16) * (SH * 2) + kk * 2);
    }

    float acc[4][4][4];
    #pragma unroll
    for (int i = 0; i < 4; i++)
        #pragma unroll
        for (int j = 0; j < 4; j++)
            #pragma unroll
            for (int r = 0; r < 4; r++) acc[i][j][r] = 0.f;

    #define LOAD_STAGE(ks, slot) do { \
        uint32_t base_ = sb + (slot) * STG_BYTES; \
        _Pragma("unroll") \
        for (int i_ = 0; i_ < 2; i_++) { \
            int c_ = i_ * 512 + tid; int r_ = c_ >> 3, q_ = c_ & 7; \
            long grow_ = mrow0 + r_; if (grow_ >= M) grow_ = M - 1; \
            const __half* s_ = A2 + grow_ * K2 + kbase + (ks) * KT + q_ * 8; \
            uint32_t d_ = base_ + (uint32_t)(r_ * (SH*2) + q_ * 16); \
            CP16(d_, s_); \
            CP16(d_ + A_HALFS*2, s_ + Kfull); \
        } \
        _Pragma("unroll") \
        for (int i_ = 0; i_ < 4; i_++) { \
            int c_ = i_ * 512 + tid; int r_ = c_ >> 3, q_ = c_ & 7; \
            const __half* s_ = B2 + (long)(nrow0 + r_) * K2 + kbase + (ks) * KT + q_ * 8; \
            uint32_t d_ = base_ + (uint32_t)(2*A_HALFS*2 + r_ * (SH*2) + q_ * 16); \
            CP16(d_, s_); \
            CP16(d_ + B_HALFS*2, s_ + Kfull); \
        } \
    } while (0)

    LOAD_STAGE(0, 0); CPCOMMIT();

    for (int it = 0; it < S; it++) {
        int slot = it & 1;
        if (it + 1 < S) { LOAD_STAGE(it + 1, (it + 1) & 1); }
        CPCOMMIT();
        CPWAIT1();
        __syncthreads();

        uint32_t stAh = sb + slot * STG_BYTES;
        uint32_t stAl = stAh + A_HALFS * 2;
        uint32_t stBh = stAh + 2 * A_HALFS * 2;
        uint32_t stBl = stBh + B_HALFS * 2;

        #pragma unroll
        for (int ks = 0; ks < 4; ks++) {
            uint32_t kb = (uint32_t)(ks * 32);
            uint32_t ah[4][4], al[4][4], bh[2][4], bl[2][4];
            #pragma unroll
            for (int mf = 0; mf < 4; mf++)
                LDSM4(ah[mf][0], ah[mf][1], ah[mf][2], ah[mf][3], stAh + aOff[mf] + kb);
            #pragma unroll
            for (int mf = 0; mf < 4; mf++)
                LDSM4(al[mf][0], al[mf][1], al[mf][2], al[mf][3], stAl + aOff[mf] + kb);
            #pragma unroll
            for (int p = 0; p < 2; p++)
                LDSM4(bh[p][0], bh[p][1], bh[p][2], bh[p][3], stBh + bOff[p] + kb);
            #pragma unroll
            for (int p = 0; p < 2; p++)
                LDSM4(bl[p][0], bl[p][1], bl[p][2], bl[p][3], stBl + bOff[p] + kb);

            #pragma unroll
            for (int mf = 0; mf < 4; mf++)
                #pragma unroll
                for (int p = 0; p < 2; p++) {
                    mma_f16(acc[mf][2*p],   ah[mf], &bh[p][0]);
                    mma_f16(acc[mf][2*p+1], ah[mf], &bh[p][2]);
                }
            #pragma unroll
            for (int mf = 0; mf < 4; mf++)
                #pragma unroll
                for (int p = 0; p < 2; p++) {
                    mma_f16(acc[mf][2*p],   ah[mf], &bl[p][0]);
                    mma_f16(acc[mf][2*p+1], ah[mf], &bl[p][2]);
                }
            #pragma unroll
            for (int mf = 0; mf < 4; mf++)
                #pragma unroll
                for (int p = 0; p < 2; p++) {
                    mma_f16(acc[mf][2*p],   al[mf], &bh[p][0]);
                    mma_f16(acc[mf][2*p+1], al[mf], &bh[p][2]);
                }
        }
        __syncthreads();
    }

    // epilogue
    #pragma unroll
    for (int mf = 0; mf < 4; mf++) {
        long r0 = mrow0 + wm * 64 + mf * 16 + g;
        long r1 = r0 + 8;
        #pragma unroll
        for (int nf = 0; nf < 4; nf++) {
            long col = nrow0 + wn * 32 + nf * 8 + 2 * tg;
            float b0 = bp ? bp[col] : 0.f, b1 = bp ? bp[col + 1] : 0.f;
            float v0 = acc[mf][nf][0] + b0, v1 = acc[mf][nf][1] + b1;
            float v2 = acc[mf][nf][2] + b0, v3 = acc[mf][nf][3] + b1;
            if (relu) {
                v0 = fmaxf(v0, 0.f); v1 = fmaxf(v1, 0.f);
                v2 = fmaxf(v2, 0.f); v3 = fmaxf(v3, 0.f);
            }
            if (Csplit) {
                __half h0, l0, h1, l1;
                if (r0 < M) {
                    split2(v0, h0, l0); split2(v1, h1, l1);
                    *(__half2*)&Csplit[r0 * (2*(long)N) + col]     = __halves2half2(h0, h1);
                    *(__half2*)&Csplit[r0 * (2*(long)N) + N + col] = __halves2half2(l0, l1);
                }
                if (r1 < M) {
                    split2(v2, h0, l0); split2(v3, h1, l1);
                    *(__half2*)&Csplit[r1 * (2*(long)N) + col]     = __halves2half2(h0, h1);
                    *(__half2*)&Csplit[r1 * (2*(long)N) + N + col] = __halves2half2(l0, l1);
                }
            } else {
                if (r0 < M) *(float2*)&C[r0 * N + col] = make_float2(v0, v1);
                if (r1 < M) *(float2*)&C[r1 * N + col] = make_float2(v2, v3);
            }
        }
    }
}

// ---------------- attention: register-tiled, d-major K, qkv input ----------
#define AT_KS   (96*WW)
#define AT_VS   (WW*97)
#define AT_PS   (32*256)
#define ATTN_SMEM ((AT_KS + AT_VS + AT_PS) * 4)   // 229,628 B

__global__ __launch_bounds__(256)
void attn2_k(const float* __restrict__ qkv, __half* __restrict__ ctx_split) {
    int b = blockIdx.x / HH, h = blockIdx.x % HH;
    extern __shared__ float smfa[];
    float* ks_t = smfa;
    float* vs   = ks_t + AT_KS;
    float* ps   = vs + AT_VS;
    float* qs   = ps;
    int tid = threadIdx.x, warp = tid >> 5, lane = tid & 31;

    for (int idx = tid; idx < WW * DHD; idx += 256) {
        int key = idx / DHD, d = idx % DHD;
        long gg = ((long)(b * WW + key)) * NQKV + h * DHD + d;
        ks_t[d * WW + key] = qkv[gg + DD];
        vs[key * 97 + d]   = qkv[gg + 2*DD];
    }
    __syncthreads();

    const float scale = 0.10206207261596575f;
    int d0 = lane * 3;

    for (int row0 = 0; row0 < 256; row0 += 32) {
        for (int idx = tid; idx < 32 * DHD; idx += 256) {
            int r = idx / DHD, d = idx % DHD;
            int row = row0 + r;
            qs[r * DHD + d] = (row < WW)
                ? qkv[((long)(b * WW + row)) * NQKV + h * DHD + d] : 0.f;
        }
        __syncthreads();

        float sc[8][4];
        #pragma unroll
        for (int kk = 0; kk < 8; kk++)
            #pragma unroll
            for (int r = 0; r < 4; r++) sc[kk][r] = 0.f;

        const float* qr = &qs[(warp * 4) * DHD];
        for (int d = 0; d < DHD; d++) {
            float q0 = qr[d], q1 = qr[DHD + d], q2 = qr[2*DHD + d], q3 = qr[3*DHD + d];
            const float* kd = &ks_t[d * WW];
            #pragma unroll
            for (int kk = 0; kk < 8; kk++) {
                float kv = kd[lane + kk * 32];
                sc[kk][0] += kv * q0;
                sc[kk][1] += kv * q1;
                sc[kk][2] += kv * q2;
                sc[kk][3] += kv * q3;
            }
        }
        __syncthreads();

        float inv[4], mx[4];
        #pragma unroll
        for (int r = 0; r < 4; r++) {
            float m = -1e30f;
            #pragma unroll
            for (int kk = 0; kk < 8; kk++) {
                int key = lane + kk * 32;
                float s = (key < WW) ? sc[kk][r] * scale : -1e30f;
                sc[kk][r] = s;
                m = fmaxf(m, s);
            }
            #pragma unroll
            for (int o = 16; o; o >>= 1) m = fmaxf(m, __shfl_xor_sync(0xffffffffu, m, o));
            mx[r] = m;
        }
        #pragma unroll
        for (int r = 0; r < 4; r++) {
            float sum = 0.f;
            #pragma unroll
            for (int kk = 0; kk < 8; kk++) {
                float e = (sc[kk][r] > -1e29f) ? __expf(sc[kk][r] - mx[r]) : 0.f;
                sc[kk][r] = e;
                sum += e;
            }
            #pragma unroll
            for (int o = 16; o; o >>= 1) sum += __shfl_xor_sync(0xffffffffu, sum, o);
            inv[r] = 1.f / sum;
        }
        #pragma unroll
        for (int r = 0; r < 4; r++)
            #pragma unroll
            for (int kk = 0; kk < 8; kk++)
                ps[(warp * 4 + r) * 256 + lane + kk * 32] = sc[kk][r] * inv[r];
        __syncwarp();

        float a0[3] = {0,0,0}, a1[3] = {0,0,0}, a2[3] = {0,0,0}, a3[3] = {0,0,0};
        const float* pr = &ps[(warp * 4) * 256];
        for (int key = 0; key < WW; key++) {
            float p0 = pr[key], p1 = pr[256 + key], p2 = pr[512 + key], p3 = pr[768 + key];
            const float* vr = &vs[key * 97 + d0];
            float vv0 = vr[0], vv1 = vr[1], vv2 = vr[2];
            a0[0] += p0*vv0; a0[1] += p0*vv1; a0[2] += p0*vv2;
            a1[0] += p1*vv0; a1[1] += p1*vv1; a1[2] += p1*vv2;
            a2[0] += p2*vv0; a2[1] += p2*vv1; a2[2] += p2*vv2;
            a3[0] += p3*vv0; a3[1] += p3*vv1; a3[2] += p3*vv2;
        }
        #pragma unroll
        for (int r = 0; r < 4; r++) {
            int row = row0 + warp * 4 + r;
            if (row < WW) {
                float* ar = (r == 0) ? a0 : (r == 1) ? a1 : (r == 2) ? a2 : a3;
                long base = ((long)(b * WW + row)) * 1536 + h * DHD + d0;
                #pragma unroll
                for (int j = 0; j < 3; j++) {
                    __half hh, ll; split2(ar[j], hh, ll);
                    ctx_split[base + j] = hh;
                    ctx_split[base + 768 + j] = ll;
                }
            }
        }
        __syncthreads();
    }
}

// ---------------- block reduce helper ---------------------------------------
__device__ __forceinline__ float block_reduce_sum(float val, float* red) {
    int lane = threadIdx.x & 31, warp = threadIdx.x >> 5;
    #pragma unroll
    for (int o = 16; o; o >>= 1) val += __shfl_xor_sync(0xffffffffu, val, o);
    if (lane == 0) red[warp] = val;
    __syncthreads();
    if (warp == 0) {
        float v = (lane < 8) ? red[lane] : 0.f;
        #pragma unroll
        for (int o = 4; o; o >>= 1) v += __shfl_xor_sync(0xffffffffu, v, o);
        if (lane == 0) red[0] = v;
    }
    __syncthreads();
    float r = red[0];
    __syncthreads();
    return r;
}

// ---------------- residual add (2 partials) + layernorm + split out ---------
__global__ __launch_bounds__(256)
void add_ln_k(const float* __restrict__ X, const float* __restrict__ Y1,
              const float* __restrict__ Y2,
              const float* __restrict__ g, const float* __restrict__ bb,
              float* __restrict__ out, __half* __restrict__ split) {
    __shared__ float red[32];
    int row = blockIdx.x, tid = threadIdx.x;
    const float* x = X + (long)row * DD;
    const float* y1 = Y1 + (long)row * DD;
    const float* y2 = Y2 + (long)row * DD;
    float v[3];
    float s = 0.f;
    #pragma unroll
    for (int i = 0; i < 3; i++) {
        int c = tid + 256 * i;
        v[i] = x[c] + y1[c] + y2[c];
        s += v[i];
    }
    float mean = block_reduce_sum(s, red) * (1.f / DD);
    float vs = 0.f;
    #pragma unroll
    for (int i = 0; i < 3; i++) { float d = v[i] - mean; vs += d * d; }
    float var = block_reduce_sum(vs, red) * (1.f / DD);
    float rstd = rsqrtf(var + 1e-5f);
    float* o = out + (long)row * DD;
    #pragma unroll
    for (int i = 0; i < 3; i++) {
        int c = tid + 256 * i;
        float val = (v[i] - mean) * rstd * g[c] + bb[c];
        o[c] = val;
        if (split) {
            __half h, l; split2(val, h, l);
            split[(long)row * 1536 + c] = h;
            split[(long)row * 1536 + 768 + c] = l;
        }
    }
}

// ---------------- final: add + LN2 + LN3 + linear(2) + softmax + argmax -----
__global__ __launch_bounds__(256)
void final2_k(const float* __restrict__ X, const float* __restrict__ Y1,
              const float* __restrict__ Y2,
              const float* __restrict__ g2, const float* __restrict__ b2,
              const float* __restrict__ g3, const float* __restrict__ b3,
              const float* __restrict__ lw, const float* __restrict__ lb,
              float* __restrict__ probs, float* __restrict__ path, int write_path) {
    __shared__ float red[32];
    int row = blockIdx.x, tid = threadIdx.x;
    const float* x = X + (long)row * DD;
    const float* y1 = Y1 + (long)row * DD;
    const float* y2 = Y2 + (long)row * DD;
    float v[3];
    float s = 0.f;
    #pragma unroll
    for (int i = 0; i < 3; i++) {
        int c = tid + 256 * i;
        v[i] = x[c] + y1[c] + y2[c];
        s += v[i];
    }
    float mean = block_reduce_sum(s, red) * (1.f / DD);
    float vs = 0.f;
    #pragma unroll
    for (int i = 0; i < 3; i++) { float d = v[i] - mean; vs += d * d; }
    float var = block_reduce_sum(vs, red) * (1.f / DD);
    float rstd = rsqrtf(var + 1e-5f);
    // LN2
    #pragma unroll
    for (int i = 0; i < 3; i++) {
        int c = tid + 256 * i;
        v[i] = (v[i] - mean) * rstd * g2[c] + b2[c];
    }
    // LN3
    s = 0.f;
    #pragma unroll
    for (int i = 0; i < 3; i++) s += v[i];
    mean = block_reduce_sum(s, red) * (1.f / DD);
    vs = 0.f;
    #pragma unroll
    for (int i = 0; i < 3; i++) { float d = v[i] - mean; vs += d * d; }
    var = block_reduce_sum(vs, red) * (1.f / DD);
    rstd = rsqrtf(var + 1e-5f);
    float l0 = 0.f, l1 = 0.f;
    #pragma unroll
    for (int i = 0; i < 3; i++) {
        int c = tid + 256 * i;
        float yv = (v[i] - mean) * rstd * g3[c] + b3[c];
        l0 += yv * lw[2 * c + 0];
        l1 += yv * lw[2 * c + 1];
    }
    l0 = block_reduce_sum(l0, red);
    l1 = block_reduce_sum(l1, red);
    if (tid == 0) {
        l0 += lb[0]; l1 += lb[1];
        float m = fmaxf(l0, l1);
        float e0 = expf(l0 - m), e1 = expf(l1 - m);
        float inv = 1.f / (e0 + e1);
        probs[2 * row + 0] = e0 * inv;
        probs[2 * row + 1] = e1 * inv;
        if (write_path) path[row] = (l1 > l0) ? 1.f : 0.f;
    }
}

// ---------------- launch -----------------------------------------------------
extern "C" void kernel_launch(void* const* d_in, const int* in_sizes, int n_in,
                              void* d_out, int out_size) {
    const float* ob  = (const float*)d_in[0];
    const int*   wi  = (const int*)d_in[1];
    const float* Wq  = (const float*)d_in[2];   const float* bq  = (const float*)d_in[3];
    const float* Wk  = (const float*)d_in[4];   const float* bk  = (const float*)d_in[5];
    const float* Wv  = (const float*)d_in[6];   const float* bv  = (const float*)d_in[7];
    const float* Wo  = (const float*)d_in[8];   const float* bo  = (const float*)d_in[9];
    const float* l1g = (const float*)d_in[10];  const float* l1b = (const float*)d_in[11];
    const float* W1f = (const float*)d_in[12];  const float* b1f = (const float*)d_in[13];
    const float* W2f = (const float*)d_in[14];  const float* b2f = (const float*)d_in[15];
    const float* l2g = (const float*)d_in[16];  const float* l2b = (const float*)d_in[17];
    const float* ng  = (const float*)d_in[18];  const float* nb  = (const float*)d_in[19];
    const float* lw  = (const float*)d_in[20];  const float* lb  = (const float*)d_in[21];

    float *feat, *qkv, *tmp, *tmp2, *x, *bqkv;
    __half *aexpA, *aexpB, *wqkvx, *wox, *w1x, *w2x;
    cudaGetSymbolAddress((void**)&feat, g_feat);
    cudaGetSymbolAddress((void**)&qkv,  g_qkv);
    cudaGetSymbolAddress((void**)&tmp,  g_tmp);
    cudaGetSymbolAddress((void**)&tmp2, g_tmp2);
    cudaGetSymbolAddress((void**)&x,    g_x);
    cudaGetSymbolAddress((void**)&bqkv, g_bqkv);
    cudaGetSymbolAddress((void**)&aexpA, g_aexpA);
    cudaGetSymbolAddress((void**)&aexpB, g_aexpB);
    cudaGetSymbolAddress((void**)&wqkvx, g_wqkv);
    cudaGetSymbolAddress((void**)&wox,  g_wo);
    cudaGetSymbolAddress((void**)&w1x,  g_w1);
    cudaGetSymbolAddress((void**)&w2x,  g_w2);

    cudaFuncSetAttribute(attn2_k, cudaFuncAttributeMaxDynamicSharedMemorySize, ATTN_SMEM);
    cudaFuncSetAttribute(gemm_f16_k, cudaFuncAttributeMaxDynamicSharedMemorySize, GEMM_SMEM);

    // 1: weight prep, 2: bias concat, 3: gather
    prep_weights_k<<<dim3(DFF/32, DFF/32, 6), 256>>>(Wq, Wk, Wv, Wo, W1f, W2f,
                                                     wqkvx, wox, w1x, w2x);
    concat_bias_k<<<3, 256>>>(bq, bk, bv, bqkv);
    gather_fused_k<<<BSZ, 256>>>(ob, wi, feat, aexpA);

    // 4: fused QKV GEMM  (N=2304, 1152 CTAs)
    gemm_f16_k<<<dim3(9, 128, 1), 512, GEMM_SMEM>>>(
        aexpA, wqkvx, bqkv, qkv, nullptr, nullptr, BW, NQKV, DD, DD, 0);

    // 5: attention (writes split ctx into aexpA)
    attn2_k<<<BSZ * HH, 256, ATTN_SMEM>>>(qkv, aexpA);

    // 6: Wo GEMM, split-K x2 (partials in tmp/tmp2)
    gemm_f16_k<<<dim3(3, 128, 2), 512, GEMM_SMEM>>>(
        aexpA, wox, bo, tmp, tmp2, nullptr, BW, DD, DD, DD/2, 0);

    // 7: LN1 (feat + tmp + tmp2; writes x + split into aexpA)
    add_ln_k<<<BW, 256>>>(feat, tmp, tmp2, l1g, l1b, x, aexpA);

    // 8: FFN1 (relu + split epilogue -> aexpB)
    gemm_f16_k<<<dim3(12, 128, 1), 512, GEMM_SMEM>>>(
        aexpA, w1x, b1f, nullptr, nullptr, aexpB, BW, DFF, DD, DD, 1);

    // 9: FFN2, split-K x2 (partials in tmp/tmp2)
    gemm_f16_k<<<dim3(3, 128, 2), 512, GEMM_SMEM>>>(
        aexpB, w2x, b2f, tmp, tmp2, nullptr, BW, DD, DFF, DFF/2, 0);

    // 10: fused add + LN2 + LN3 + linear + softmax + argmax
    float* probs = (float*)d_out;
    float* path  = probs + (long)BW * 2;
    int wp = (out_size >= BW * 3) ? 1 : 0;
    final2_k<<<BW, 256>>>(x, tmp, tmp2, l2g, l2b, ng, nb, lw, lb, probs, path, wp);
}